// round 2
// baseline (speedup 1.0000x reference)
#include <cuda_runtime.h>
#include <cstdint>

// ---------------------------------------------------------------------------
// KANExpert: two KAN linear layers.
// Each layer = one GEMM over an expanded K dim:  K' = in_features * 9
//   lane j=0  : silu(x[n,i]) paired with base_w[o,i]
//   lane j=1-8: cubic B-spline basis B_{j-1}(x[n,i]) paired with
//               spline_w[o,i,j-1] * scaler[o,i]
//
// Shapes:
//   x:  (4096, 512)
//   L1: M=4096, N=2049 (pad 2176), K=512*9=4608
//   L2: M=4096, N=512,             K=2049*9=18441 (pad 18448)
// ---------------------------------------------------------------------------

#define NROWS 4096          // token count (fixed)
#define IN1   512
#define OUT1  2049
#define NP1   2176          // OUT1 padded to multiple of 128
#define K1    4608          // IN1*9, already multiple of 16
#define IN2   2049
#define OUT2  512
#define NP2   512
#define K2R   18441         // IN2*9 (real)
#define K2    18448         // padded to multiple of 16

// Scratch (device globals — no allocation allowed in kernel_launch)
__device__ float g_AT1[(size_t)K1 * NROWS];   // 75.5 MB  A^T layer1: [k][n]
__device__ float g_WT1[(size_t)K1 * NP1];     // 40.1 MB  W^T layer1: [k][o]
__device__ float g_H  [(size_t)NROWS * NP1];  // 35.6 MB  hidden [n][o], stride NP1
__device__ float g_AT2[(size_t)K2 * NROWS];   // 302  MB  A^T layer2
__device__ float g_WT2[(size_t)K2 * NP2];     // 37.8 MB  W^T layer2

// ---------------------------------------------------------------------------
// B-spline basis (grid_size=5, order=3, range [-1,1]) + SiLU.
// Grid values and denominators are compile-time constants after unrolling,
// so all divisions constant-fold into multiplies.
// ---------------------------------------------------------------------------
__device__ __forceinline__ void kan_expand9(float x, float v[9]) {
    float g[12];
#pragma unroll
    for (int t = 0; t < 12; t++) g[t] = (float)(t - 3) * 0.4f + (-1.0f);

    float b[11];
#pragma unroll
    for (int t = 0; t < 11; t++) b[t] = (x >= g[t] && x < g[t + 1]) ? 1.0f : 0.0f;

#pragma unroll
    for (int k = 1; k <= 3; k++) {
#pragma unroll
        for (int t = 0; t < 11 - k; t++) {
            float left  = (x - g[t]) / (g[t + k] - g[t]) * b[t];
            float right = (g[t + k + 1] - x) / (g[t + k + 1] - g[t + 1]) * b[t + 1];
            b[t] = left + right;
        }
    }
    v[0] = x / (1.0f + expf(-x));   // SiLU
#pragma unroll
    for (int j = 0; j < 8; j++) v[j + 1] = b[j];
}

// Expand activations X[n][i] (row stride ldx) -> AT[(i*9+j)][n]
__global__ void expand_A_kernel(const float* __restrict__ X,
                                float* __restrict__ AT,
                                int IN, int ldx, int total) {
    int t = blockIdx.x * blockDim.x + threadIdx.x;
    if (t >= total) return;
    int n = t & (NROWS - 1);
    int i = t >> 12;                 // / 4096
    float x = X[(size_t)n * ldx + i];
    float v[9];
    kan_expand9(x, v);
    size_t base = (size_t)(i * 9) * NROWS + n;
#pragma unroll
    for (int j = 0; j < 9; j++) AT[base + (size_t)j * NROWS] = v[j];
}

// Expand weights -> WT[(i*9+j)][o], o padded to Np (pad cols zeroed)
__global__ void expand_W_kernel(const float* __restrict__ BW,
                                const float* __restrict__ SW,
                                const float* __restrict__ SC,
                                float* __restrict__ WT,
                                int OUT, int IN, int Np, int total) {
    int t = blockIdx.x * blockDim.x + threadIdx.x;
    if (t >= total) return;
    int o = t % Np;
    int i = t / Np;
    size_t base = (size_t)(i * 9) * Np + o;
    if (o >= OUT) {
#pragma unroll
        for (int j = 0; j < 9; j++) WT[base + (size_t)j * Np] = 0.0f;
        return;
    }
    size_t oi = (size_t)o * IN + i;
    float s = SC[oi];
    WT[base] = BW[oi];
    const float* sw = SW + oi * 8;
#pragma unroll
    for (int j = 0; j < 8; j++) WT[base + (size_t)(j + 1) * Np] = sw[j] * s;
}

__global__ void zero_fill_kernel(float* __restrict__ p, int count) {
    int t = blockIdx.x * blockDim.x + threadIdx.x;
    if (t < count) p[t] = 0.0f;
}

// ---------------------------------------------------------------------------
// Classic shared-memory SGEMM.
//   C[M][N] = A^T(K x M, k-major) * B(K x N, k-major)
//   M mult of BM, N mult of BN, K mult of BK. 256 threads, TM x TN per thread.
// ---------------------------------------------------------------------------
template <int BM, int BN, int BK, int TM, int TN>
__global__ void __launch_bounds__(256)
sgemm_kernel(int M, int N, int K,
             const float* __restrict__ A,
             const float* __restrict__ B,
             float* __restrict__ C) {
    __shared__ float As[BK][BM];
    __shared__ float Bs[BK][BN];

    const int tid  = threadIdx.x;
    constexpr int TCOLS = BN / TN;            // threads per row of C tile
    const int tcol = tid % TCOLS;
    const int trow = tid / TCOLS;

    const float* Ag = A + (size_t)blockIdx.y * BM;
    const float* Bg = B + (size_t)blockIdx.x * BN;

    float acc[TM][TN];
#pragma unroll
    for (int i = 0; i < TM; i++)
#pragma unroll
        for (int j = 0; j < TN; j++) acc[i][j] = 0.0f;

    constexpr int A4 = BK * BM / 4;
    constexpr int B4 = BK * BN / 4;

    for (int k0 = 0; k0 < K; k0 += BK) {
#pragma unroll
        for (int idx = tid; idx < A4; idx += 256) {
            int r = idx / (BM / 4);
            int c = (idx % (BM / 4)) * 4;
            *(float4*)&As[r][c] =
                *(const float4*)(Ag + (size_t)(k0 + r) * M + c);
        }
#pragma unroll
        for (int idx = tid; idx < B4; idx += 256) {
            int r = idx / (BN / 4);
            int c = (idx % (BN / 4)) * 4;
            *(float4*)&Bs[r][c] =
                *(const float4*)(Bg + (size_t)(k0 + r) * N + c);
        }
        __syncthreads();

#pragma unroll
        for (int kk = 0; kk < BK; kk++) {
            float ra[TM], rb[TN];
#pragma unroll
            for (int i = 0; i < TM; i += 4)
                *(float4*)&ra[i] = *(const float4*)&As[kk][trow * TM + i];
#pragma unroll
            for (int j = 0; j < TN; j += 4)
                *(float4*)&rb[j] = *(const float4*)&Bs[kk][tcol * TN + j];
#pragma unroll
            for (int i = 0; i < TM; i++)
#pragma unroll
                for (int j = 0; j < TN; j++)
                    acc[i][j] = fmaf(ra[i], rb[j], acc[i][j]);
        }
        __syncthreads();
    }

#pragma unroll
    for (int i = 0; i < TM; i++) {
        float* Crow = C + (size_t)(blockIdx.y * BM + trow * TM + i) * N
                        + (size_t)blockIdx.x * BN + tcol * TN;
#pragma unroll
        for (int j = 0; j < TN; j += 4) {
            *(float4*)(Crow + j) =
                make_float4(acc[i][j], acc[i][j + 1], acc[i][j + 2], acc[i][j + 3]);
        }
    }
}

// ---------------------------------------------------------------------------
extern "C" void kernel_launch(void* const* d_in, const int* in_sizes, int n_in,
                              void* d_out, int out_size) {
    const float* x   = (const float*)d_in[0];
    const float* bw1 = (const float*)d_in[1];
    const float* sw1 = (const float*)d_in[2];
    const float* sc1 = (const float*)d_in[3];
    const float* bw2 = (const float*)d_in[4];
    const float* sw2 = (const float*)d_in[5];
    const float* sc2 = (const float*)d_in[6];
    float* out = (float*)d_out;

    float *AT1, *WT1, *H, *AT2, *WT2;
    cudaGetSymbolAddress((void**)&AT1, g_AT1);
    cudaGetSymbolAddress((void**)&WT1, g_WT1);
    cudaGetSymbolAddress((void**)&H,   g_H);
    cudaGetSymbolAddress((void**)&AT2, g_AT2);
    cudaGetSymbolAddress((void**)&WT2, g_WT2);

    const int TB = 256;

    // ---------------- Layer 1 ----------------
    {
        int totalA = NROWS * IN1;                               // 2M
        expand_A_kernel<<<(totalA + TB - 1) / TB, TB>>>(x, AT1, IN1, IN1, totalA);

        int totalW = NP1 * IN1;                                 // 2176*512
        expand_W_kernel<<<(totalW + TB - 1) / TB, TB>>>(bw1, sw1, sc1, WT1,
                                                        OUT1, IN1, NP1, totalW);

        dim3 grid(NP1 / 128, NROWS / 128);                      // (17, 32)
        sgemm_kernel<128, 128, 16, 8, 8><<<grid, 256>>>(NROWS, NP1, K1, AT1, WT1, H);
    }

    // ---------------- Layer 2 ----------------
    {
        int totalA = NROWS * IN2;                               // 4096*2049
        expand_A_kernel<<<(totalA + TB - 1) / TB, TB>>>(H, AT2, IN2, NP1, totalA);

        // zero pad rows of AT2: k in [K2R, K2)
        int padA = (K2 - K2R) * NROWS;                          // 7*4096
        zero_fill_kernel<<<(padA + TB - 1) / TB, TB>>>(AT2 + (size_t)K2R * NROWS, padA);

        int totalW = NP2 * IN2;                                 // 512*2049
        expand_W_kernel<<<(totalW + TB - 1) / TB, TB>>>(bw2, sw2, sc2, WT2,
                                                        OUT2, IN2, NP2, totalW);
        int padW = (K2 - K2R) * NP2;                            // 7*512
        zero_fill_kernel<<<(padW + TB - 1) / TB, TB>>>(WT2 + (size_t)K2R * NP2, padW);

        dim3 grid(NP2 / 64, NROWS / 128);                       // (8, 32)
        sgemm_kernel<128, 64, 16, 8, 4><<<grid, 256>>>(NROWS, NP2, K2, AT2, WT2, out);
    }
}

// round 3
// speedup vs baseline: 1.0007x; 1.0007x over previous
#include <cuda_runtime.h>
#include <cstdint>

// ---------------------------------------------------------------------------
// KANExpert: two KAN linear layers.
// Each layer = one GEMM over an expanded K dim:  K' = in_features * 9
//   lane j=0  : silu(x[n,i]) paired with base_w[o,i]
//   lane j=1-8: cubic B-spline basis B_{j-1}(x[n,i]) paired with
//               spline_w[o,i,j-1] * scaler[o,i]
//
// Shapes:
//   x:  (4096, 512)
//   L1: M=4096, N=2049 (pad 2176), K=512*9=4608
//   L2: M=4096, N=512,             K=2049*9=18441 (pad 18448)
// ---------------------------------------------------------------------------

#define NROWS 4096          // token count (fixed)
#define IN1   512
#define OUT1  2049
#define NP1   2176          // OUT1 padded to multiple of 128
#define K1    4608          // IN1*9, already multiple of 16
#define IN2   2049
#define OUT2  512
#define NP2   512
#define K2R   18441         // IN2*9 (real)
#define K2    18448         // padded to multiple of 16

// Scratch (device globals — no allocation allowed in kernel_launch)
__device__ float g_AT1[(size_t)K1 * NROWS];   // 75.5 MB  A^T layer1: [k][n]
__device__ float g_WT1[(size_t)K1 * NP1];     // 40.1 MB  W^T layer1: [k][o]
__device__ float g_H  [(size_t)NROWS * NP1];  // 35.6 MB  hidden [n][o], stride NP1
__device__ float g_AT2[(size_t)K2 * NROWS];   // 302  MB  A^T layer2
__device__ float g_WT2[(size_t)K2 * NP2];     // 37.8 MB  W^T layer2

// ---------------------------------------------------------------------------
// B-spline basis (grid_size=5, order=3, range [-1,1]) + SiLU.
// Grid values and denominators are compile-time constants after unrolling,
// so all divisions constant-fold into multiplies.
// ---------------------------------------------------------------------------
__device__ __forceinline__ void kan_expand9(float x, float v[9]) {
    float g[12];
#pragma unroll
    for (int t = 0; t < 12; t++) g[t] = (float)(t - 3) * 0.4f + (-1.0f);

    float b[11];
#pragma unroll
    for (int t = 0; t < 11; t++) b[t] = (x >= g[t] && x < g[t + 1]) ? 1.0f : 0.0f;

#pragma unroll
    for (int k = 1; k <= 3; k++) {
#pragma unroll
        for (int t = 0; t < 11 - k; t++) {
            float left  = (x - g[t]) / (g[t + k] - g[t]) * b[t];
            float right = (g[t + k + 1] - x) / (g[t + k + 1] - g[t + 1]) * b[t + 1];
            b[t] = left + right;
        }
    }
    v[0] = x / (1.0f + expf(-x));   // SiLU
#pragma unroll
    for (int j = 0; j < 8; j++) v[j + 1] = b[j];
}

// Expand activations X[n][i] (row stride ldx) -> AT[(i*9+j)][n]
__global__ void expand_A_kernel(const float* __restrict__ X,
                                float* __restrict__ AT,
                                int IN, int ldx, int total) {
    int t = blockIdx.x * blockDim.x + threadIdx.x;
    if (t >= total) return;
    int n = t & (NROWS - 1);
    int i = t >> 12;                 // / 4096
    float x = X[(size_t)n * ldx + i];
    float v[9];
    kan_expand9(x, v);
    size_t base = (size_t)(i * 9) * NROWS + n;
#pragma unroll
    for (int j = 0; j < 9; j++) AT[base + (size_t)j * NROWS] = v[j];
}

// Expand weights -> WT[(i*9+j)][o], o padded to Np (pad cols zeroed)
__global__ void expand_W_kernel(const float* __restrict__ BW,
                                const float* __restrict__ SW,
                                const float* __restrict__ SC,
                                float* __restrict__ WT,
                                int OUT, int IN, int Np, int total) {
    int t = blockIdx.x * blockDim.x + threadIdx.x;
    if (t >= total) return;
    int o = t % Np;
    int i = t / Np;
    size_t base = (size_t)(i * 9) * Np + o;
    if (o >= OUT) {
#pragma unroll
        for (int j = 0; j < 9; j++) WT[base + (size_t)j * Np] = 0.0f;
        return;
    }
    size_t oi = (size_t)o * IN + i;
    float s = SC[oi];
    WT[base] = BW[oi];
    const float* sw = SW + oi * 8;
#pragma unroll
    for (int j = 0; j < 8; j++) WT[base + (size_t)(j + 1) * Np] = sw[j] * s;
}

__global__ void zero_fill_kernel(float* __restrict__ p, int count) {
    int t = blockIdx.x * blockDim.x + threadIdx.x;
    if (t < count) p[t] = 0.0f;
}

// ---------------------------------------------------------------------------
// Classic shared-memory SGEMM.
//   C[M][N] = A^T(K x M, k-major) * B(K x N, k-major)
//   M mult of BM, N mult of BN, K mult of BK. 256 threads, TM x TN per thread.
// ---------------------------------------------------------------------------
template <int BM, int BN, int BK, int TM, int TN>
__global__ void __launch_bounds__(256)
sgemm_kernel(int M, int N, int K,
             const float* __restrict__ A,
             const float* __restrict__ B,
             float* __restrict__ C) {
    __shared__ float As[BK][BM];
    __shared__ float Bs[BK][BN];

    const int tid  = threadIdx.x;
    constexpr int TCOLS = BN / TN;            // threads per row of C tile
    const int tcol = tid % TCOLS;
    const int trow = tid / TCOLS;

    const float* Ag = A + (size_t)blockIdx.y * BM;
    const float* Bg = B + (size_t)blockIdx.x * BN;

    float acc[TM][TN];
#pragma unroll
    for (int i = 0; i < TM; i++)
#pragma unroll
        for (int j = 0; j < TN; j++) acc[i][j] = 0.0f;

    constexpr int A4 = BK * BM / 4;
    constexpr int B4 = BK * BN / 4;

    for (int k0 = 0; k0 < K; k0 += BK) {
#pragma unroll
        for (int idx = tid; idx < A4; idx += 256) {
            int r = idx / (BM / 4);
            int c = (idx % (BM / 4)) * 4;
            *(float4*)&As[r][c] =
                *(const float4*)(Ag + (size_t)(k0 + r) * M + c);
        }
#pragma unroll
        for (int idx = tid; idx < B4; idx += 256) {
            int r = idx / (BN / 4);
            int c = (idx % (BN / 4)) * 4;
            *(float4*)&Bs[r][c] =
                *(const float4*)(Bg + (size_t)(k0 + r) * N + c);
        }
        __syncthreads();

#pragma unroll
        for (int kk = 0; kk < BK; kk++) {
            float ra[TM], rb[TN];
#pragma unroll
            for (int i = 0; i < TM; i += 4)
                *(float4*)&ra[i] = *(const float4*)&As[kk][trow * TM + i];
#pragma unroll
            for (int j = 0; j < TN; j += 4)
                *(float4*)&rb[j] = *(const float4*)&Bs[kk][tcol * TN + j];
#pragma unroll
            for (int i = 0; i < TM; i++)
#pragma unroll
                for (int j = 0; j < TN; j++)
                    acc[i][j] = fmaf(ra[i], rb[j], acc[i][j]);
        }
        __syncthreads();
    }

#pragma unroll
    for (int i = 0; i < TM; i++) {
        float* Crow = C + (size_t)(blockIdx.y * BM + trow * TM + i) * N
                        + (size_t)blockIdx.x * BN + tcol * TN;
#pragma unroll
        for (int j = 0; j < TN; j += 4) {
            *(float4*)(Crow + j) =
                make_float4(acc[i][j], acc[i][j + 1], acc[i][j + 2], acc[i][j + 3]);
        }
    }
}

// ---------------------------------------------------------------------------
extern "C" void kernel_launch(void* const* d_in, const int* in_sizes, int n_in,
                              void* d_out, int out_size) {
    const float* x   = (const float*)d_in[0];
    const float* bw1 = (const float*)d_in[1];
    const float* sw1 = (const float*)d_in[2];
    const float* sc1 = (const float*)d_in[3];
    const float* bw2 = (const float*)d_in[4];
    const float* sw2 = (const float*)d_in[5];
    const float* sc2 = (const float*)d_in[6];
    float* out = (float*)d_out;

    float *AT1, *WT1, *H, *AT2, *WT2;
    cudaGetSymbolAddress((void**)&AT1, g_AT1);
    cudaGetSymbolAddress((void**)&WT1, g_WT1);
    cudaGetSymbolAddress((void**)&H,   g_H);
    cudaGetSymbolAddress((void**)&AT2, g_AT2);
    cudaGetSymbolAddress((void**)&WT2, g_WT2);

    const int TB = 256;

    // ---------------- Layer 1 ----------------
    {
        int totalA = NROWS * IN1;                               // 2M
        expand_A_kernel<<<(totalA + TB - 1) / TB, TB>>>(x, AT1, IN1, IN1, totalA);

        int totalW = NP1 * IN1;                                 // 2176*512
        expand_W_kernel<<<(totalW + TB - 1) / TB, TB>>>(bw1, sw1, sc1, WT1,
                                                        OUT1, IN1, NP1, totalW);

        dim3 grid(NP1 / 128, NROWS / 128);                      // (17, 32)
        sgemm_kernel<128, 128, 16, 8, 8><<<grid, 256>>>(NROWS, NP1, K1, AT1, WT1, H);
    }

    // ---------------- Layer 2 ----------------
    {
        int totalA = NROWS * IN2;                               // 4096*2049
        expand_A_kernel<<<(totalA + TB - 1) / TB, TB>>>(H, AT2, IN2, NP1, totalA);

        // zero pad rows of AT2: k in [K2R, K2)
        int padA = (K2 - K2R) * NROWS;                          // 7*4096
        zero_fill_kernel<<<(padA + TB - 1) / TB, TB>>>(AT2 + (size_t)K2R * NROWS, padA);

        int totalW = NP2 * IN2;                                 // 512*2049
        expand_W_kernel<<<(totalW + TB - 1) / TB, TB>>>(bw2, sw2, sc2, WT2,
                                                        OUT2, IN2, NP2, totalW);
        int padW = (K2 - K2R) * NP2;                            // 7*512
        zero_fill_kernel<<<(padW + TB - 1) / TB, TB>>>(WT2 + (size_t)K2R * NP2, padW);

        dim3 grid(NP2 / 64, NROWS / 128);                       // (8, 32)
        sgemm_kernel<128, 64, 16, 8, 4><<<grid, 256>>>(NROWS, NP2, K2, AT2, WT2, out);
    }
}

// round 5
// speedup vs baseline: 1.7829x; 1.7816x over previous
#include <cuda_runtime.h>
#include <cuda_bf16.h>
#include <cstdint>

#define MROWS 4096
#define IN1   512
#define OUT1  2049
#define NPAD1 2304
#define KP1   4608          // IN1*9
#define IN2   2049
#define OUT2  512
#define KR2   18441         // IN2*9
#define KP2   18496         // padded, 578 chunks of 32

__device__ __align__(128) __nv_bfloat16 g_A1[2ull * MROWS * KP1];
__device__ __align__(128) __nv_bfloat16 g_B1[2ull * NPAD1 * KP1];
__device__ __align__(128) float         g_H [(size_t)MROWS * NPAD1];
__device__ __align__(128) __nv_bfloat16 g_A2[2ull * MROWS * KP2];
__device__ __align__(128) __nv_bfloat16 g_B2[2ull * OUT2 * KP2];

// ------------------------------------------------------------- helpers
__device__ __forceinline__ uint32_t smem_u32(const void* p) {
    uint32_t a;
    asm("{ .reg .u64 t; cvta.to.shared.u64 t, %1; cvt.u32.u64 %0, t; }" : "=r"(a) : "l"(p));
    return a;
}
__device__ __forceinline__ void cp16(uint32_t dst, const void* src) {
    asm volatile("cp.async.cg.shared.global [%0], [%1], 16;" :: "r"(dst), "l"(src) : "memory");
}
__device__ __forceinline__ void ldm_x4(uint32_t a, uint32_t& r0, uint32_t& r1,
                                       uint32_t& r2, uint32_t& r3) {
    asm volatile("ldmatrix.sync.aligned.m8n8.x4.shared.b16 {%0,%1,%2,%3}, [%4];"
                 : "=r"(r0), "=r"(r1), "=r"(r2), "=r"(r3) : "r"(a));
}
__device__ __forceinline__ void mma16816(float* d, const uint32_t* a, const uint32_t* b) {
    asm volatile(
        "mma.sync.aligned.m16n8k16.row.col.f32.bf16.bf16.f32 "
        "{%0,%1,%2,%3}, {%4,%5,%6,%7}, {%8,%9}, {%0,%1,%2,%3};"
        : "+f"(d[0]), "+f"(d[1]), "+f"(d[2]), "+f"(d[3])
        : "r"(a[0]), "r"(a[1]), "r"(a[2]), "r"(a[3]), "r"(b[0]), "r"(b[1]));
}

// ------------------------------------------------------------- expansion
__device__ __forceinline__ void expand9(float x, float v[9]) {
#pragma unroll
    for (int j = 0; j < 9; j++) v[j] = 0.0f;
    v[0] = x / (1.0f + __expf(-x));                       // SiLU
    if (x >= -2.2f && x < 2.2f) {                         // uniform cubic B-spline
        float xm = (x + 2.2f) * 2.5f;
        float fm = floorf(xm);
        int s = (int)fm;
        float u = xm - fm, u2 = u * u, u3 = u2 * u, w = 1.0f - u;
        float nn[4];
        nn[0] = w * w * w * (1.0f / 6.0f);
        nn[1] = fmaf(u3, 0.5f, fmaf(u2, -1.0f, 2.0f / 3.0f));
        nn[2] = fmaf(u3, -0.5f, fmaf(u2, 0.5f, fmaf(u, 0.5f, 1.0f / 6.0f)));
        nn[3] = u3 * (1.0f / 6.0f);
#pragma unroll
        for (int d = 0; d < 4; d++) {
            int t = s - 3 + d;
            if ((unsigned)t < 8u) v[1 + t] = nn[d];
        }
    }
}
__device__ __forceinline__ void wsplit(float f, __nv_bfloat16& h, __nv_bfloat16& l) {
    h = __float2bfloat16(f);                              // rn
    l = __float2bfloat16(f - __bfloat162float(h));
}

__global__ void expA(const float* __restrict__ X, int ldx, int IN, int KP,
                     __nv_bfloat16* __restrict__ A, size_t PS, int total) {
    int t = blockIdx.x * blockDim.x + threadIdx.x;
    if (t >= total) return;
    int n = t / IN, i = t - n * IN;
    float v[9];
    expand9(X[(size_t)n * ldx + i], v);
    size_t o = (size_t)n * KP + i * 9;
#pragma unroll
    for (int j = 0; j < 9; j++) {
        __nv_bfloat16 h, l; wsplit(v[j], h, l);
        A[o + j] = h; A[PS + o + j] = l;
    }
}

__global__ void expW(const float* __restrict__ BW, const float* __restrict__ SW,
                     const float* __restrict__ SC, int OUT, int IN, int KP,
                     __nv_bfloat16* __restrict__ B, size_t PS, int total) {
    int t = blockIdx.x * blockDim.x + threadIdx.x;
    if (t >= total) return;
    int o = t / IN, i = t - o * IN;
    size_t ob = (size_t)o * KP + i * 9;
    __nv_bfloat16 z = __float2bfloat16(0.0f);
    if (o >= OUT) {
#pragma unroll
        for (int j = 0; j < 9; j++) { B[ob + j] = z; B[PS + ob + j] = z; }
        return;
    }
    size_t oi = (size_t)o * IN + i;
    float s = SC[oi];
    const float* sw = SW + oi * 8;
    __nv_bfloat16 h, l;
    wsplit(BW[oi], h, l); B[ob] = h; B[PS + ob] = l;
#pragma unroll
    for (int j = 0; j < 8; j++) {
        wsplit(sw[j] * s, h, l);
        B[ob + 1 + j] = h; B[PS + ob + 1 + j] = l;
    }
}

__global__ void ztail(__nv_bfloat16* __restrict__ A, size_t PS, int KP, int K0, int rows) {
    int per = KP - K0;
    int t = blockIdx.x * blockDim.x + threadIdx.x;
    if (t >= rows * per) return;
    int r = t / per, c = t - r * per;
    size_t o = (size_t)r * KP + K0 + c;
    __nv_bfloat16 z = __float2bfloat16(0.0f);
    A[o] = z; A[PS + o] = z;
}

// ------------------------------------------------------------- MMA GEMM
// D[M][Nld] (fp32) = A @ B^T. A: [M][KP] bf16 k-contig, hi plane + lo at +APS.
// B: [N][KP] likewise. fp32 accuracy via 3-pass hi/lo split.
// CTA: BM x BN, 256 threads (8 warps, 2m x 4n), BK=32, 3-stage cp.async.
template <int BM, int BN>
__global__ void __launch_bounds__(256, 1)
gemm_mma(const __nv_bfloat16* __restrict__ A, size_t APS,
         const __nv_bfloat16* __restrict__ B, size_t BPS,
         float* __restrict__ C, int Nld, int KP, int KITERS) {
    constexpr int WM = BM / 2;            // 64
    constexpr int WN = BN / 4;            // 32 | 16
    constexpr int MT = WM / 16;           // 4
    constexpr int NT = WN / 8;            // 4 | 2
    constexpr int LDS = 80;               // smem bytes/row (32 bf16 + 8 pad)
    constexpr int SA = BM * LDS;
    constexpr int SB = BN * LDS;
    constexpr int STAGE = 2 * SA + 2 * SB;
    constexpr int NCHK = (BM + BN) * 8 / 256;

    extern __shared__ __align__(16) char smc[];
    const uint32_t sbase = smem_u32(smc);
    const int tid = threadIdx.x;
    const int lane = tid & 31, wid = tid >> 5;
    const int wm = wid >> 2, wn = wid & 3;
    const int row0 = blockIdx.y * BM, col0 = blockIdx.x * BN;

    // per-thread cp.async chunk plan
    const __nv_bfloat16* gsrc[NCHK];
    uint32_t sdst[NCHK];
#pragma unroll
    for (int j = 0; j < NCHK; j++) {
        int id = tid + 256 * j;
        if (id < BM * 8) {
            int p = id / (BM * 4), rid = id - p * BM * 4;
            int r = rid >> 2, c = rid & 3;
            sdst[j] = p * SA + r * LDS + c * 16;
            gsrc[j] = A + (size_t)p * APS + (size_t)(row0 + r) * KP + c * 8;
        } else {
            int id2 = id - BM * 8;
            int p = id2 / (BN * 4), rid = id2 - p * BN * 4;
            int r = rid >> 2, c = rid & 3;
            sdst[j] = 2 * SA + p * SB + r * LDS + c * 16;
            gsrc[j] = B + (size_t)p * BPS + (size_t)(col0 + r) * KP + c * 8;
        }
    }

    auto load = [&](int stg, int it) {
        uint32_t sb = sbase + stg * STAGE;
        size_t ko = (size_t)it * 32;
#pragma unroll
        for (int j = 0; j < NCHK; j++) cp16(sb + sdst[j], gsrc[j] + ko);
        asm volatile("cp.async.commit_group;" ::: "memory");
    };

    // ldmatrix lane offsets within a stage
    uint32_t offA[MT], offB[NT / 2];
#pragma unroll
    for (int mt = 0; mt < MT; mt++)
        offA[mt] = (uint32_t)((wm * WM + mt * 16 + (lane & 15)) * LDS + ((lane >> 4) * 16));
#pragma unroll
    for (int np = 0; np < NT / 2; np++)
        offB[np] = (uint32_t)(2 * SA +
                   (wn * WN + np * 16 + ((lane >> 4) * 8) + (lane & 7)) * LDS +
                   (((lane >> 3) & 1) * 16));

    float acc[MT][NT][4];
#pragma unroll
    for (int i = 0; i < MT; i++)
#pragma unroll
        for (int j = 0; j < NT; j++)
#pragma unroll
            for (int k = 0; k < 4; k++) acc[i][j][k] = 0.0f;

    load(0, 0);
    load(1, 1);

    for (int it = 0; it < KITERS; it++) {
        const int stg = it % 3;
        if (it + 1 < KITERS) asm volatile("cp.async.wait_group 1;" ::: "memory");
        else                 asm volatile("cp.async.wait_group 0;" ::: "memory");
        __syncthreads();
        if (it + 2 < KITERS) load((it + 2) % 3, it + 2);

        const uint32_t sb = sbase + stg * STAGE;
#pragma unroll
        for (int s = 0; s < 2; s++) {
            uint32_t ah[MT][4], al[MT][4], bh[NT][2], bl[NT][2];
#pragma unroll
            for (int mt = 0; mt < MT; mt++) {
                uint32_t a0 = sb + offA[mt] + s * 32;
                ldm_x4(a0, ah[mt][0], ah[mt][1], ah[mt][2], ah[mt][3]);
                ldm_x4(a0 + SA, al[mt][0], al[mt][1], al[mt][2], al[mt][3]);
            }
#pragma unroll
            for (int np = 0; np < NT / 2; np++) {
                uint32_t b0 = sb + offB[np] + s * 32;
                ldm_x4(b0, bh[2 * np][0], bh[2 * np][1], bh[2 * np + 1][0], bh[2 * np + 1][1]);
                ldm_x4(b0 + SB, bl[2 * np][0], bl[2 * np][1], bl[2 * np + 1][0], bl[2 * np + 1][1]);
            }
#pragma unroll
            for (int mt = 0; mt < MT; mt++)
#pragma unroll
                for (int nt = 0; nt < NT; nt++) {
                    mma16816(acc[mt][nt], ah[mt], bh[nt]);
                    mma16816(acc[mt][nt], ah[mt], bl[nt]);
                    mma16816(acc[mt][nt], al[mt], bh[nt]);
                }
        }
    }

    // epilogue
#pragma unroll
    for (int mt = 0; mt < MT; mt++)
#pragma unroll
        for (int nt = 0; nt < NT; nt++) {
            int r = row0 + wm * WM + mt * 16 + (lane >> 2);
            int c = col0 + wn * WN + nt * 8 + ((lane & 3) << 1);
            *(float2*)&C[(size_t)r * Nld + c] = make_float2(acc[mt][nt][0], acc[mt][nt][1]);
            *(float2*)&C[(size_t)(r + 8) * Nld + c] = make_float2(acc[mt][nt][2], acc[mt][nt][3]);
        }
}

// ---------------------------------------------------------------------------
extern "C" void kernel_launch(void* const* d_in, const int* in_sizes, int n_in,
                              void* d_out, int out_size) {
    const float* x   = (const float*)d_in[0];
    const float* bw1 = (const float*)d_in[1];
    const float* sw1 = (const float*)d_in[2];
    const float* sc1 = (const float*)d_in[3];
    const float* bw2 = (const float*)d_in[4];
    const float* sw2 = (const float*)d_in[5];
    const float* sc2 = (const float*)d_in[6];
    float* out = (float*)d_out;

    __nv_bfloat16 *A1, *B1, *A2, *B2;
    float* H;
    cudaGetSymbolAddress((void**)&A1, g_A1);
    cudaGetSymbolAddress((void**)&B1, g_B1);
    cudaGetSymbolAddress((void**)&H,  g_H);
    cudaGetSymbolAddress((void**)&A2, g_A2);
    cudaGetSymbolAddress((void**)&B2, g_B2);

    const size_t PA1 = (size_t)MROWS * KP1, PB1 = (size_t)NPAD1 * KP1;
    const size_t PA2 = (size_t)MROWS * KP2, PB2 = (size_t)OUT2 * KP2;
    const int TB = 256;

    const int SM1 = 3 * (2 * 128 * 80 + 2 * 128 * 80);   // 122880
    const int SM2 = 3 * (2 * 128 * 80 + 2 * 64 * 80);    //  92160
    cudaFuncSetAttribute(gemm_mma<128, 128>, cudaFuncAttributeMaxDynamicSharedMemorySize, SM1);
    cudaFuncSetAttribute(gemm_mma<128, 64>,  cudaFuncAttributeMaxDynamicSharedMemorySize, SM2);

    // -------- Layer 1 --------
    {
        int tA = MROWS * IN1;
        expA<<<(tA + TB - 1) / TB, TB>>>(x, IN1, IN1, KP1, A1, PA1, tA);
        int tW = NPAD1 * IN1;
        expW<<<(tW + TB - 1) / TB, TB>>>(bw1, sw1, sc1, OUT1, IN1, KP1, B1, PB1, tW);
        gemm_mma<128, 128><<<dim3(NPAD1 / 128, MROWS / 128), 256, SM1>>>(
            A1, PA1, B1, PB1, H, NPAD1, KP1, KP1 / 32);
    }
    // -------- Layer 2 --------
    {
        int tA = MROWS * IN2;
        expA<<<(tA + TB - 1) / TB, TB>>>(H, NPAD1, IN2, KP2, A2, PA2, tA);
        int zA = MROWS * (KP2 - KR2);
        ztail<<<(zA + TB - 1) / TB, TB>>>(A2, PA2, KP2, KR2, MROWS);
        int tW = OUT2 * IN2;
        expW<<<(tW + TB - 1) / TB, TB>>>(bw2, sw2, sc2, OUT2, IN2, KP2, B2, PB2, tW);
        int zW = OUT2 * (KP2 - KR2);
        ztail<<<(zW + TB - 1) / TB, TB>>>(B2, PB2, KP2, KR2, OUT2);
        gemm_mma<128, 64><<<dim3(OUT2 / 64, MROWS / 128), 256, SM2>>>(
            A2, PA2, B2, PB2, out, OUT2, KP2, KP2 / 32);
    }
}

// round 6
// speedup vs baseline: 2.4243x; 1.3598x over previous
#include <cuda_runtime.h>
#include <cuda_bf16.h>
#include <cstdint>

#define MROWS 4096
#define IN1   512
#define OUT1  2049
#define NPAD1 2304
#define KP1   4608          // IN1*9
#define IN2   2049
#define OUT2  512
#define KR2   18441         // IN2*9
#define KP2   18496         // padded, 578 chunks of 32

__device__ __align__(128) __nv_bfloat16 g_A1[2ull * MROWS * KP1];
__device__ __align__(128) __nv_bfloat16 g_B1[2ull * NPAD1 * KP1];
__device__ __align__(128) float         g_H [(size_t)MROWS * NPAD1];
__device__ __align__(128) __nv_bfloat16 g_A2[2ull * MROWS * KP2];
__device__ __align__(128) __nv_bfloat16 g_B2[2ull * OUT2 * KP2];

// ------------------------------------------------------------- helpers
__device__ __forceinline__ uint32_t smem_u32(const void* p) {
    uint32_t a;
    asm("{ .reg .u64 t; cvta.to.shared.u64 t, %1; cvt.u32.u64 %0, t; }" : "=r"(a) : "l"(p));
    return a;
}
__device__ __forceinline__ void cp16(uint32_t dst, const void* src) {
    asm volatile("cp.async.cg.shared.global [%0], [%1], 16;" :: "r"(dst), "l"(src) : "memory");
}
__device__ __forceinline__ void ldm_x4(uint32_t a, uint32_t& r0, uint32_t& r1,
                                       uint32_t& r2, uint32_t& r3) {
    asm volatile("ldmatrix.sync.aligned.m8n8.x4.shared.b16 {%0,%1,%2,%3}, [%4];"
                 : "=r"(r0), "=r"(r1), "=r"(r2), "=r"(r3) : "r"(a));
}
__device__ __forceinline__ void mma16816(float* d, const uint32_t* a, const uint32_t* b) {
    asm volatile(
        "mma.sync.aligned.m16n8k16.row.col.f32.bf16.bf16.f32 "
        "{%0,%1,%2,%3}, {%4,%5,%6,%7}, {%8,%9}, {%0,%1,%2,%3};"
        : "+f"(d[0]), "+f"(d[1]), "+f"(d[2]), "+f"(d[3])
        : "r"(a[0]), "r"(a[1]), "r"(a[2]), "r"(a[3]), "r"(b[0]), "r"(b[1]));
}

// ------------------------------------------------------------- expansion math
__device__ __forceinline__ void expand9(float x, float v[9]) {
#pragma unroll
    for (int j = 0; j < 9; j++) v[j] = 0.0f;
    v[0] = x / (1.0f + __expf(-x));                       // SiLU
    if (x >= -2.2f && x < 2.2f) {                         // uniform cubic B-spline
        float xm = (x + 2.2f) * 2.5f;
        float fm = floorf(xm);
        int s = (int)fm;
        float u = xm - fm, u2 = u * u, u3 = u2 * u, w = 1.0f - u;
        float nn[4];
        nn[0] = w * w * w * (1.0f / 6.0f);
        nn[1] = fmaf(u3, 0.5f, fmaf(u2, -1.0f, 2.0f / 3.0f));
        nn[2] = fmaf(u3, -0.5f, fmaf(u2, 0.5f, fmaf(u, 0.5f, 1.0f / 6.0f)));
        nn[3] = u3 * (1.0f / 6.0f);
#pragma unroll
        for (int d = 0; d < 4; d++) {
            int t = s - 3 + d;
            if ((unsigned)t < 8u) v[1 + t] = nn[d];
        }
    }
}
__device__ __forceinline__ void wsplit(float f, __nv_bfloat16& h, __nv_bfloat16& l) {
    h = __float2bfloat16(f);                              // rn
    l = __float2bfloat16(f - __bfloat162float(h));
}

// ------------------------------------------------------------- expansion kernels
// One warp expands 32 consecutive i of one row into smem, then writes the
// 288-element (576 B) span per plane with coalesced 16 B stores. The K pad
// tail (span clamp) is zero-filled by invalid lanes, so no separate ztail.
__global__ void __launch_bounds__(256)
expA(const float* __restrict__ X, int ldx, int IN, int KP, int CPR,
     __nv_bfloat16* __restrict__ A, size_t PS, int nwarps) {
    __shared__ __align__(16) __nv_bfloat16 sh[8][288];
    __shared__ __align__(16) __nv_bfloat16 sl[8][288];
    int wl = threadIdx.x >> 5, lane = threadIdx.x & 31;
    int w = blockIdx.x * 8 + wl;
    if (w >= nwarps) return;
    int row = w / CPR, ic = w - row * CPR;
    int i0 = ic * 32, i = i0 + lane;
    float v[9];
    if (i < IN) expand9(X[(size_t)row * ldx + i], v);
    else {
#pragma unroll
        for (int j = 0; j < 9; j++) v[j] = 0.0f;
    }
#pragma unroll
    for (int j = 0; j < 9; j++) {
        __nv_bfloat16 h, l; wsplit(v[j], h, l);
        sh[wl][lane * 9 + j] = h; sl[wl][lane * 9 + j] = l;
    }
    __syncwarp();
    int span = KP - i0 * 9; if (span > 288) span = 288;
    int n4 = span >> 3;
    const uint4* s0 = (const uint4*)sh[wl];
    const uint4* s1 = (const uint4*)sl[wl];
    uint4* d0 = (uint4*)(A + (size_t)row * KP + i0 * 9);
    uint4* d1 = (uint4*)(A + PS + (size_t)row * KP + i0 * 9);
    for (int idx = lane; idx < n4; idx += 32) { d0[idx] = s0[idx]; d1[idx] = s1[idx]; }
}

__global__ void __launch_bounds__(256)
expW(const float* __restrict__ BW, const float* __restrict__ SW,
     const float* __restrict__ SC, int OUT, int IN, int KP, int CPR,
     __nv_bfloat16* __restrict__ B, size_t PS, int nwarps) {
    __shared__ __align__(16) __nv_bfloat16 sh[8][288];
    __shared__ __align__(16) __nv_bfloat16 sl[8][288];
    int wl = threadIdx.x >> 5, lane = threadIdx.x & 31;
    int w = blockIdx.x * 8 + wl;
    if (w >= nwarps) return;
    int o = w / CPR, ic = w - o * CPR;
    int i0 = ic * 32, i = i0 + lane;
    float v[9];
    if (i < IN && o < OUT) {
        size_t oi = (size_t)o * IN + i;
        float s = SC[oi];
        v[0] = BW[oi];
        const float* sw = SW + oi * 8;
#pragma unroll
        for (int j = 0; j < 8; j++) v[1 + j] = sw[j] * s;
    } else {
#pragma unroll
        for (int j = 0; j < 9; j++) v[j] = 0.0f;
    }
#pragma unroll
    for (int j = 0; j < 9; j++) {
        __nv_bfloat16 h, l; wsplit(v[j], h, l);
        sh[wl][lane * 9 + j] = h; sl[wl][lane * 9 + j] = l;
    }
    __syncwarp();
    int span = KP - i0 * 9; if (span > 288) span = 288;
    int n4 = span >> 3;
    const uint4* s0 = (const uint4*)sh[wl];
    const uint4* s1 = (const uint4*)sl[wl];
    uint4* d0 = (uint4*)(B + (size_t)o * KP + i0 * 9);
    uint4* d1 = (uint4*)(B + PS + (size_t)o * KP + i0 * 9);
    for (int idx = lane; idx < n4; idx += 32) { d0[idx] = s0[idx]; d1[idx] = s1[idx]; }
}

// ------------------------------------------------------------- MMA GEMM
// D[M][Nld] (fp32) = A @ B^T. A: [M][KP] bf16 k-contig, hi plane + lo at +APS.
// B: [N][KP] likewise. fp32 accuracy via 3-pass hi/lo split.
// CTA: BM x BN, 256 threads (8 warps, 2m x 4n), BK=32, 3-stage cp.async.
template <int BM, int BN>
__global__ void __launch_bounds__(256, 1)
gemm_mma(const __nv_bfloat16* __restrict__ A, size_t APS,
         const __nv_bfloat16* __restrict__ B, size_t BPS,
         float* __restrict__ C, int Nld, int KP, int KITERS) {
    constexpr int WM = BM / 2;            // 64
    constexpr int WN = BN / 4;            // 32
    constexpr int MT = WM / 16;           // 4
    constexpr int NT = WN / 8;            // 4
    constexpr int LDS = 80;               // smem bytes/row (32 bf16 + 8 pad)
    constexpr int SA = BM * LDS;
    constexpr int SB = BN * LDS;
    constexpr int STAGE = 2 * SA + 2 * SB;
    constexpr int NCHK = (BM + BN) * 8 / 256;

    extern __shared__ __align__(16) char smc[];
    const uint32_t sbase = smem_u32(smc);
    const int tid = threadIdx.x;
    const int lane = tid & 31, wid = tid >> 5;
    const int wm = wid >> 2, wn = wid & 3;
    const int row0 = blockIdx.y * BM, col0 = blockIdx.x * BN;

    // per-thread cp.async chunk plan
    const __nv_bfloat16* gsrc[NCHK];
    uint32_t sdst[NCHK];
#pragma unroll
    for (int j = 0; j < NCHK; j++) {
        int id = tid + 256 * j;
        if (id < BM * 8) {
            int p = id / (BM * 4), rid = id - p * BM * 4;
            int r = rid >> 2, c = rid & 3;
            sdst[j] = p * SA + r * LDS + c * 16;
            gsrc[j] = A + (size_t)p * APS + (size_t)(row0 + r) * KP + c * 8;
        } else {
            int id2 = id - BM * 8;
            int p = id2 / (BN * 4), rid = id2 - p * BN * 4;
            int r = rid >> 2, c = rid & 3;
            sdst[j] = 2 * SA + p * SB + r * LDS + c * 16;
            gsrc[j] = B + (size_t)p * BPS + (size_t)(col0 + r) * KP + c * 8;
        }
    }

    auto load = [&](int stg, int it) {
        uint32_t sb = sbase + stg * STAGE;
        size_t ko = (size_t)it * 32;
#pragma unroll
        for (int j = 0; j < NCHK; j++) cp16(sb + sdst[j], gsrc[j] + ko);
        asm volatile("cp.async.commit_group;" ::: "memory");
    };

    // ldmatrix lane offsets within a stage
    uint32_t offA[MT], offB[NT / 2];
#pragma unroll
    for (int mt = 0; mt < MT; mt++)
        offA[mt] = (uint32_t)((wm * WM + mt * 16 + (lane & 15)) * LDS + ((lane >> 4) * 16));
#pragma unroll
    for (int np = 0; np < NT / 2; np++)
        offB[np] = (uint32_t)(2 * SA +
                   (wn * WN + np * 16 + ((lane >> 4) * 8) + (lane & 7)) * LDS +
                   (((lane >> 3) & 1) * 16));

    float acc[MT][NT][4];
#pragma unroll
    for (int i = 0; i < MT; i++)
#pragma unroll
        for (int j = 0; j < NT; j++)
#pragma unroll
            for (int k = 0; k < 4; k++) acc[i][j][k] = 0.0f;

    load(0, 0);
    load(1, 1);

    for (int it = 0; it < KITERS; it++) {
        const int stg = it % 3;
        if (it + 1 < KITERS) asm volatile("cp.async.wait_group 1;" ::: "memory");
        else                 asm volatile("cp.async.wait_group 0;" ::: "memory");
        __syncthreads();
        if (it + 2 < KITERS) load((it + 2) % 3, it + 2);

        const uint32_t sb = sbase + stg * STAGE;
#pragma unroll
        for (int s = 0; s < 2; s++) {
            uint32_t ah[MT][4], al[MT][4], bh[NT][2], bl[NT][2];
#pragma unroll
            for (int mt = 0; mt < MT; mt++) {
                uint32_t a0 = sb + offA[mt] + s * 32;
                ldm_x4(a0, ah[mt][0], ah[mt][1], ah[mt][2], ah[mt][3]);
                ldm_x4(a0 + SA, al[mt][0], al[mt][1], al[mt][2], al[mt][3]);
            }
#pragma unroll
            for (int np = 0; np < NT / 2; np++) {
                uint32_t b0 = sb + offB[np] + s * 32;
                ldm_x4(b0, bh[2 * np][0], bh[2 * np][1], bh[2 * np + 1][0], bh[2 * np + 1][1]);
                ldm_x4(b0 + SB, bl[2 * np][0], bl[2 * np][1], bl[2 * np + 1][0], bl[2 * np + 1][1]);
            }
#pragma unroll
            for (int mt = 0; mt < MT; mt++)
#pragma unroll
                for (int nt = 0; nt < NT; nt++) {
                    mma16816(acc[mt][nt], ah[mt], bh[nt]);
                    mma16816(acc[mt][nt], ah[mt], bl[nt]);
                    mma16816(acc[mt][nt], al[mt], bh[nt]);
                }
        }
    }

    // epilogue
#pragma unroll
    for (int mt = 0; mt < MT; mt++)
#pragma unroll
        for (int nt = 0; nt < NT; nt++) {
            int r = row0 + wm * WM + mt * 16 + (lane >> 2);
            int c = col0 + wn * WN + nt * 8 + ((lane & 3) << 1);
            *(float2*)&C[(size_t)r * Nld + c] = make_float2(acc[mt][nt][0], acc[mt][nt][1]);
            *(float2*)&C[(size_t)(r + 8) * Nld + c] = make_float2(acc[mt][nt][2], acc[mt][nt][3]);
        }
}

// ---------------------------------------------------------------------------
extern "C" void kernel_launch(void* const* d_in, const int* in_sizes, int n_in,
                              void* d_out, int out_size) {
    const float* x   = (const float*)d_in[0];
    const float* bw1 = (const float*)d_in[1];
    const float* sw1 = (const float*)d_in[2];
    const float* sc1 = (const float*)d_in[3];
    const float* bw2 = (const float*)d_in[4];
    const float* sw2 = (const float*)d_in[5];
    const float* sc2 = (const float*)d_in[6];
    float* out = (float*)d_out;

    __nv_bfloat16 *A1, *B1, *A2, *B2;
    float* H;
    cudaGetSymbolAddress((void**)&A1, g_A1);
    cudaGetSymbolAddress((void**)&B1, g_B1);
    cudaGetSymbolAddress((void**)&H,  g_H);
    cudaGetSymbolAddress((void**)&A2, g_A2);
    cudaGetSymbolAddress((void**)&B2, g_B2);

    const size_t PA1 = (size_t)MROWS * KP1, PB1 = (size_t)NPAD1 * KP1;
    const size_t PA2 = (size_t)MROWS * KP2, PB2 = (size_t)OUT2 * KP2;

    const int SM1 = 3 * (2 * 128 * 80 + 2 * 128 * 80);   // 122880
    cudaFuncSetAttribute(gemm_mma<128, 128>, cudaFuncAttributeMaxDynamicSharedMemorySize, SM1);

    // -------- Layer 1 --------
    {
        int cpr = (IN1 + 31) / 32;                        // 16
        int nw = MROWS * cpr;
        expA<<<(nw + 7) / 8, 256>>>(x, IN1, IN1, KP1, cpr, A1, PA1, nw);
        int nww = NPAD1 * cpr;
        expW<<<(nww + 7) / 8, 256>>>(bw1, sw1, sc1, OUT1, IN1, KP1, cpr, B1, PB1, nww);
        gemm_mma<128, 128><<<dim3(NPAD1 / 128, MROWS / 128), 256, SM1>>>(
            A1, PA1, B1, PB1, H, NPAD1, KP1, KP1 / 32);
    }
    // -------- Layer 2 --------
    {
        int cpr = (IN2 + 31) / 32;                        // 65
        int nw = MROWS * cpr;
        expA<<<(nw + 7) / 8, 256>>>(H, NPAD1, IN2, KP2, cpr, A2, PA2, nw);
        int nww = OUT2 * cpr;
        expW<<<(nww + 7) / 8, 256>>>(bw2, sw2, sc2, OUT2, IN2, KP2, cpr, B2, PB2, nww);
        gemm_mma<128, 128><<<dim3(OUT2 / 128, MROWS / 128), 256, SM1>>>(
            A2, PA2, B2, PB2, out, OUT2, KP2, KP2 / 32);
    }
}

// round 7
// speedup vs baseline: 2.5605x; 1.0562x over previous
#include <cuda_runtime.h>
#include <cuda_bf16.h>
#include <cstdint>

#define MROWS 4096
#define IN1   512
#define OUT1  2049
#define NPAD1 2304
#define KP1   4608          // IN1*9
#define IN2   2049
#define OUT2  512
#define KR2   18441         // IN2*9
#define KP2   18496         // padded, 578 chunks of 32

__device__ __align__(128) __nv_bfloat16 g_A1[2ull * MROWS * KP1];
__device__ __align__(128) __nv_bfloat16 g_B1[2ull * NPAD1 * KP1];
__device__ __align__(128) float         g_H [(size_t)MROWS * NPAD1];
__device__ __align__(128) __nv_bfloat16 g_A2[2ull * MROWS * KP2];
__device__ __align__(128) __nv_bfloat16 g_B2[2ull * OUT2 * KP2];

// ------------------------------------------------------------- helpers
__device__ __forceinline__ uint32_t smem_u32(const void* p) {
    uint32_t a;
    asm("{ .reg .u64 t; cvta.to.shared.u64 t, %1; cvt.u32.u64 %0, t; }" : "=r"(a) : "l"(p));
    return a;
}
__device__ __forceinline__ void cp16(uint32_t dst, const void* src) {
    asm volatile("cp.async.cg.shared.global [%0], [%1], 16;" :: "r"(dst), "l"(src) : "memory");
}
__device__ __forceinline__ void ldm_x4(uint32_t a, uint32_t& r0, uint32_t& r1,
                                       uint32_t& r2, uint32_t& r3) {
    asm volatile("ldmatrix.sync.aligned.m8n8.x4.shared.b16 {%0,%1,%2,%3}, [%4];"
                 : "=r"(r0), "=r"(r1), "=r"(r2), "=r"(r3) : "r"(a));
}
__device__ __forceinline__ void mma16816(float* d, const uint32_t* a, const uint32_t* b) {
    asm volatile(
        "mma.sync.aligned.m16n8k16.row.col.f32.bf16.bf16.f32 "
        "{%0,%1,%2,%3}, {%4,%5,%6,%7}, {%8,%9}, {%0,%1,%2,%3};"
        : "+f"(d[0]), "+f"(d[1]), "+f"(d[2]), "+f"(d[3])
        : "r"(a[0]), "r"(a[1]), "r"(a[2]), "r"(a[3]), "r"(b[0]), "r"(b[1]));
}

// ------------------------------------------------------------- expansion math
__device__ __forceinline__ void expand9(float x, float v[9]) {
#pragma unroll
    for (int j = 0; j < 9; j++) v[j] = 0.0f;
    v[0] = x / (1.0f + __expf(-x));                       // SiLU
    if (x >= -2.2f && x < 2.2f) {                         // uniform cubic B-spline
        float xm = (x + 2.2f) * 2.5f;
        float fm = floorf(xm);
        int s = (int)fm;
        float u = xm - fm, u2 = u * u, u3 = u2 * u, w = 1.0f - u;
        float nn[4];
        nn[0] = w * w * w * (1.0f / 6.0f);
        nn[1] = fmaf(u3, 0.5f, fmaf(u2, -1.0f, 2.0f / 3.0f));
        nn[2] = fmaf(u3, -0.5f, fmaf(u2, 0.5f, fmaf(u, 0.5f, 1.0f / 6.0f)));
        nn[3] = u3 * (1.0f / 6.0f);
#pragma unroll
        for (int d = 0; d < 4; d++) {
            int t = s - 3 + d;
            if ((unsigned)t < 8u) v[1 + t] = nn[d];
        }
    }
}
__device__ __forceinline__ void wsplit(float f, __nv_bfloat16& h, __nv_bfloat16& l) {
    h = __float2bfloat16(f);                              // rn
    l = __float2bfloat16(f - __bfloat162float(h));
}

// ------------------------------------------------------------- expansion kernels
__global__ void __launch_bounds__(256)
expA(const float* __restrict__ X, int ldx, int IN, int KP, int CPR,
     __nv_bfloat16* __restrict__ A, size_t PS, int nwarps) {
    __shared__ __align__(16) __nv_bfloat16 sh[8][288];
    __shared__ __align__(16) __nv_bfloat16 sl[8][288];
    int wl = threadIdx.x >> 5, lane = threadIdx.x & 31;
    int w = blockIdx.x * 8 + wl;
    if (w >= nwarps) return;
    int row = w / CPR, ic = w - row * CPR;
    int i0 = ic * 32, i = i0 + lane;
    float v[9];
    if (i < IN) expand9(X[(size_t)row * ldx + i], v);
    else {
#pragma unroll
        for (int j = 0; j < 9; j++) v[j] = 0.0f;
    }
#pragma unroll
    for (int j = 0; j < 9; j++) {
        __nv_bfloat16 h, l; wsplit(v[j], h, l);
        sh[wl][lane * 9 + j] = h; sl[wl][lane * 9 + j] = l;
    }
    __syncwarp();
    int span = KP - i0 * 9; if (span > 288) span = 288;
    int n4 = span >> 3;
    const uint4* s0 = (const uint4*)sh[wl];
    const uint4* s1 = (const uint4*)sl[wl];
    uint4* d0 = (uint4*)(A + (size_t)row * KP + i0 * 9);
    uint4* d1 = (uint4*)(A + PS + (size_t)row * KP + i0 * 9);
    for (int idx = lane; idx < n4; idx += 32) { d0[idx] = s0[idx]; d1[idx] = s1[idx]; }
}

__global__ void __launch_bounds__(256)
expW(const float* __restrict__ BW, const float* __restrict__ SW,
     const float* __restrict__ SC, int OUT, int IN, int KP, int CPR,
     __nv_bfloat16* __restrict__ B, size_t PS, int nwarps) {
    __shared__ __align__(16) __nv_bfloat16 sh[8][288];
    __shared__ __align__(16) __nv_bfloat16 sl[8][288];
    int wl = threadIdx.x >> 5, lane = threadIdx.x & 31;
    int w = blockIdx.x * 8 + wl;
    if (w >= nwarps) return;
    int o = w / CPR, ic = w - o * CPR;
    int i0 = ic * 32, i = i0 + lane;
    float v[9];
    if (i < IN && o < OUT) {
        size_t oi = (size_t)o * IN + i;
        float s = SC[oi];
        v[0] = BW[oi];
        const float* sw = SW + oi * 8;
#pragma unroll
        for (int j = 0; j < 8; j++) v[1 + j] = sw[j] * s;
    } else {
#pragma unroll
        for (int j = 0; j < 9; j++) v[j] = 0.0f;
    }
#pragma unroll
    for (int j = 0; j < 9; j++) {
        __nv_bfloat16 h, l; wsplit(v[j], h, l);
        sh[wl][lane * 9 + j] = h; sl[wl][lane * 9 + j] = l;
    }
    __syncwarp();
    int span = KP - i0 * 9; if (span > 288) span = 288;
    int n4 = span >> 3;
    const uint4* s0 = (const uint4*)sh[wl];
    const uint4* s1 = (const uint4*)sl[wl];
    uint4* d0 = (uint4*)(B + (size_t)o * KP + i0 * 9);
    uint4* d1 = (uint4*)(B + PS + (size_t)o * KP + i0 * 9);
    for (int idx = lane; idx < n4; idx += 32) { d0[idx] = s0[idx]; d1[idx] = s1[idx]; }
}

// ------------------------------------------------------------- MMA GEMM
// D[M][Nld] (fp32) = A @ B^T. A: [M][KP] bf16 k-contig, hi plane + lo at +APS.
// B: [N][KP] likewise. fp32 accuracy via 3-pass hi/lo split.
// CTA: BM x BN, 256 threads (8 warps, 2m x 4n), warp WM=64 x WN=BN/4,
// BK=32, 3-stage cp.async.
template <int BM, int BN>
__global__ void __launch_bounds__(256, 1)
gemm_mma(const __nv_bfloat16* __restrict__ A, size_t APS,
         const __nv_bfloat16* __restrict__ B, size_t BPS,
         float* __restrict__ C, int Nld, int KP, int KITERS) {
    constexpr int WM = BM / 2;            // 64
    constexpr int WN = BN / 4;            // 32 | 64
    constexpr int MT = WM / 16;           // 4
    constexpr int NT = WN / 8;            // 4 | 8
    constexpr int LDS = 80;               // smem bytes/row (32 bf16 + 8 pad)
    constexpr int SA = BM * LDS;
    constexpr int SB = BN * LDS;
    constexpr int STAGE = 2 * SA + 2 * SB;
    constexpr int NCHK = (BM + BN) * 8 / 256;

    extern __shared__ __align__(16) char smc[];
    const uint32_t sbase = smem_u32(smc);
    const int tid = threadIdx.x;
    const int lane = tid & 31, wid = tid >> 5;
    const int wm = wid >> 2, wn = wid & 3;
    const int row0 = blockIdx.y * BM, col0 = blockIdx.x * BN;

    // per-thread cp.async plan: u32 byte offsets + A/B select bitmask
    const char* baseA = (const char*)(A + (size_t)row0 * KP);
    const char* baseB = (const char*)(B + (size_t)col0 * KP);
    uint32_t goff[NCHK], sdst[NCHK], selA = 0;
#pragma unroll
    for (int j = 0; j < NCHK; j++) {
        int id = tid + 256 * j;
        if (id < BM * 8) {
            int p = id / (BM * 4), rid = id - p * BM * 4;
            int r = rid >> 2, c = rid & 3;
            sdst[j] = p * SA + r * LDS + c * 16;
            goff[j] = (uint32_t)((size_t)p * APS * 2 + (size_t)r * KP * 2 + c * 16);
            selA |= 1u << j;
        } else {
            int id2 = id - BM * 8;
            int p = id2 / (BN * 4), rid = id2 - p * BN * 4;
            int r = rid >> 2, c = rid & 3;
            sdst[j] = 2 * SA + p * SB + r * LDS + c * 16;
            goff[j] = (uint32_t)((size_t)p * BPS * 2 + (size_t)r * KP * 2 + c * 16);
        }
    }

    auto load = [&](int stg, int it) {
        uint32_t sb = sbase + stg * STAGE;
        uint32_t ko = (uint32_t)it * 64;   // bytes (32 bf16)
#pragma unroll
        for (int j = 0; j < NCHK; j++) {
            const char* base = (selA >> j) & 1 ? baseA : baseB;
            cp16(sb + sdst[j], base + goff[j] + ko);
        }
        asm volatile("cp.async.commit_group;" ::: "memory");
    };

    // ldmatrix lane offsets within a stage
    uint32_t offA[MT], offB[NT / 2];
#pragma unroll
    for (int mt = 0; mt < MT; mt++)
        offA[mt] = (uint32_t)((wm * WM + mt * 16 + (lane & 15)) * LDS + ((lane >> 4) * 16));
#pragma unroll
    for (int np = 0; np < NT / 2; np++)
        offB[np] = (uint32_t)(2 * SA +
                   (wn * WN + np * 16 + ((lane >> 4) * 8) + (lane & 7)) * LDS +
                   (((lane >> 3) & 1) * 16));

    float acc[MT][NT][4];
#pragma unroll
    for (int i = 0; i < MT; i++)
#pragma unroll
        for (int j = 0; j < NT; j++)
#pragma unroll
            for (int k = 0; k < 4; k++) acc[i][j][k] = 0.0f;

    load(0, 0);
    load(1, 1);

    for (int it = 0; it < KITERS; it++) {
        const int stg = it % 3;
        if (it + 1 < KITERS) asm volatile("cp.async.wait_group 1;" ::: "memory");
        else                 asm volatile("cp.async.wait_group 0;" ::: "memory");
        __syncthreads();
        if (it + 2 < KITERS) load((it + 2) % 3, it + 2);

        const uint32_t sb = sbase + stg * STAGE;
#pragma unroll
        for (int s = 0; s < 2; s++) {
            uint32_t ah[MT][4], al[MT][4];
#pragma unroll
            for (int mt = 0; mt < MT; mt++) {
                uint32_t a0 = sb + offA[mt] + s * 32;
                ldm_x4(a0, ah[mt][0], ah[mt][1], ah[mt][2], ah[mt][3]);
                ldm_x4(a0 + SA, al[mt][0], al[mt][1], al[mt][2], al[mt][3]);
            }
#pragma unroll
            for (int np = 0; np < NT / 2; np++) {
                uint32_t bh[2][2], bl[2][2];
                uint32_t b0 = sb + offB[np] + s * 32;
                ldm_x4(b0, bh[0][0], bh[0][1], bh[1][0], bh[1][1]);
                ldm_x4(b0 + SB, bl[0][0], bl[0][1], bl[1][0], bl[1][1]);
#pragma unroll
                for (int q = 0; q < 2; q++) {
                    int nt = 2 * np + q;
#pragma unroll
                    for (int mt = 0; mt < MT; mt++) {
                        mma16816(acc[mt][nt], ah[mt], bh[q]);
                        mma16816(acc[mt][nt], ah[mt], bl[q]);
                        mma16816(acc[mt][nt], al[mt], bh[q]);
                    }
                }
            }
        }
    }

    // epilogue
#pragma unroll
    for (int mt = 0; mt < MT; mt++)
#pragma unroll
        for (int nt = 0; nt < NT; nt++) {
            int r = row0 + wm * WM + mt * 16 + (lane >> 2);
            int c = col0 + wn * WN + nt * 8 + ((lane & 3) << 1);
            *(float2*)&C[(size_t)r * Nld + c] = make_float2(acc[mt][nt][0], acc[mt][nt][1]);
            *(float2*)&C[(size_t)(r + 8) * Nld + c] = make_float2(acc[mt][nt][2], acc[mt][nt][3]);
        }
}

// ---------------------------------------------------------------------------
extern "C" void kernel_launch(void* const* d_in, const int* in_sizes, int n_in,
                              void* d_out, int out_size) {
    const float* x   = (const float*)d_in[0];
    const float* bw1 = (const float*)d_in[1];
    const float* sw1 = (const float*)d_in[2];
    const float* sc1 = (const float*)d_in[3];
    const float* bw2 = (const float*)d_in[4];
    const float* sw2 = (const float*)d_in[5];
    const float* sc2 = (const float*)d_in[6];
    float* out = (float*)d_out;

    __nv_bfloat16 *A1, *B1, *A2, *B2;
    float* H;
    cudaGetSymbolAddress((void**)&A1, g_A1);
    cudaGetSymbolAddress((void**)&B1, g_B1);
    cudaGetSymbolAddress((void**)&H,  g_H);
    cudaGetSymbolAddress((void**)&A2, g_A2);
    cudaGetSymbolAddress((void**)&B2, g_B2);

    const size_t PA1 = (size_t)MROWS * KP1, PB1 = (size_t)NPAD1 * KP1;
    const size_t PA2 = (size_t)MROWS * KP2, PB2 = (size_t)OUT2 * KP2;

    const int SM1 = 3 * (2 * 128 * 80 + 2 * 256 * 80);   // 184320
    const int SM2 = 3 * (2 * 128 * 80 + 2 * 128 * 80);   // 122880
    cudaFuncSetAttribute(gemm_mma<128, 256>, cudaFuncAttributeMaxDynamicSharedMemorySize, SM1);
    cudaFuncSetAttribute(gemm_mma<128, 128>, cudaFuncAttributeMaxDynamicSharedMemorySize, SM2);

    // -------- Layer 1 --------
    {
        int cpr = (IN1 + 31) / 32;                        // 16
        int nw = MROWS * cpr;
        expA<<<(nw + 7) / 8, 256>>>(x, IN1, IN1, KP1, cpr, A1, PA1, nw);
        int nww = NPAD1 * cpr;
        expW<<<(nww + 7) / 8, 256>>>(bw1, sw1, sc1, OUT1, IN1, KP1, cpr, B1, PB1, nww);
        gemm_mma<128, 256><<<dim3(NPAD1 / 256, MROWS / 128), 256, SM1>>>(
            A1, PA1, B1, PB1, H, NPAD1, KP1, KP1 / 32);
    }
    // -------- Layer 2 --------
    {
        int cpr = (IN2 + 31) / 32;                        // 65
        int nw = MROWS * cpr;
        expA<<<(nw + 7) / 8, 256>>>(H, NPAD1, IN2, KP2, cpr, A2, PA2, nw);
        int nww = OUT2 * cpr;
        expW<<<(nww + 7) / 8, 256>>>(bw2, sw2, sc2, OUT2, IN2, KP2, cpr, B2, PB2, nww);
        gemm_mma<128, 128><<<dim3(OUT2 / 128, MROWS / 128), 256, SM2>>>(
            A2, PA2, B2, PB2, out, OUT2, KP2, KP2 / 32);
    }
}

// round 8
// speedup vs baseline: 2.5703x; 1.0038x over previous
#include <cuda_runtime.h>
#include <cuda_bf16.h>
#include <cstdint>

#define MROWS 4096
#define IN1   512
#define OUT1  2049
#define NPAD1 2304
#define KP1   4608          // IN1*9
#define IN2   2049
#define OUT2  512
#define KR2   18441         // IN2*9
#define KP2   18496         // padded, 578 chunks of 32

__device__ __align__(128) __nv_bfloat16 g_A1[2ull * MROWS * KP1];
__device__ __align__(128) __nv_bfloat16 g_B1[2ull * NPAD1 * KP1];
__device__ __align__(128) float         g_H [(size_t)MROWS * NPAD1];
__device__ __align__(128) __nv_bfloat16 g_A2[2ull * MROWS * KP2];
__device__ __align__(128) __nv_bfloat16 g_B2[2ull * OUT2 * KP2];

// ------------------------------------------------------------- helpers
__device__ __forceinline__ uint32_t smem_u32(const void* p) {
    uint32_t a;
    asm("{ .reg .u64 t; cvta.to.shared.u64 t, %1; cvt.u32.u64 %0, t; }" : "=r"(a) : "l"(p));
    return a;
}
__device__ __forceinline__ void cp16(uint32_t dst, const void* src) {
    asm volatile("cp.async.cg.shared.global [%0], [%1], 16;" :: "r"(dst), "l"(src) : "memory");
}
__device__ __forceinline__ void ldm_x4(uint32_t a, uint32_t& r0, uint32_t& r1,
                                       uint32_t& r2, uint32_t& r3) {
    asm volatile("ldmatrix.sync.aligned.m8n8.x4.shared.b16 {%0,%1,%2,%3}, [%4];"
                 : "=r"(r0), "=r"(r1), "=r"(r2), "=r"(r3) : "r"(a));
}
__device__ __forceinline__ void mma16816(float* d, const uint32_t* a, const uint32_t* b) {
    asm volatile(
        "mma.sync.aligned.m16n8k16.row.col.f32.bf16.bf16.f32 "
        "{%0,%1,%2,%3}, {%4,%5,%6,%7}, {%8,%9}, {%0,%1,%2,%3};"
        : "+f"(d[0]), "+f"(d[1]), "+f"(d[2]), "+f"(d[3])
        : "r"(a[0]), "r"(a[1]), "r"(a[2]), "r"(a[3]), "r"(b[0]), "r"(b[1]));
}

// ------------------------------------------------------------- expansion math
__device__ __forceinline__ void expand9(float x, float v[9]) {
#pragma unroll
    for (int j = 0; j < 9; j++) v[j] = 0.0f;
    v[0] = x / (1.0f + __expf(-x));                       // SiLU
    if (x >= -2.2f && x < 2.2f) {                         // uniform cubic B-spline
        float xm = (x + 2.2f) * 2.5f;
        float fm = floorf(xm);
        int s = (int)fm;
        float u = xm - fm, u2 = u * u, u3 = u2 * u, w = 1.0f - u;
        float nn[4];
        nn[0] = w * w * w * (1.0f / 6.0f);
        nn[1] = fmaf(u3, 0.5f, fmaf(u2, -1.0f, 2.0f / 3.0f));
        nn[2] = fmaf(u3, -0.5f, fmaf(u2, 0.5f, fmaf(u, 0.5f, 1.0f / 6.0f)));
        nn[3] = u3 * (1.0f / 6.0f);
#pragma unroll
        for (int d = 0; d < 4; d++) {
            int t = s - 3 + d;
            if ((unsigned)t < 8u) v[1 + t] = nn[d];
        }
    }
}
__device__ __forceinline__ void wsplit(float f, __nv_bfloat16& h, __nv_bfloat16& l) {
    h = __float2bfloat16(f);                              // rn
    l = __float2bfloat16(f - __bfloat162float(h));
}

// ------------------------------------------------------------- expansion kernels
__global__ void __launch_bounds__(256)
expA(const float* __restrict__ X, int ldx, int IN, int KP, int CPR,
     __nv_bfloat16* __restrict__ A, size_t PS, int nwarps) {
    __shared__ __align__(16) __nv_bfloat16 sh[8][288];
    __shared__ __align__(16) __nv_bfloat16 sl[8][288];
    int wl = threadIdx.x >> 5, lane = threadIdx.x & 31;
    int w = blockIdx.x * 8 + wl;
    if (w >= nwarps) return;
    int row = w / CPR, ic = w - row * CPR;
    int i0 = ic * 32, i = i0 + lane;
    float v[9];
    if (i < IN) expand9(X[(size_t)row * ldx + i], v);
    else {
#pragma unroll
        for (int j = 0; j < 9; j++) v[j] = 0.0f;
    }
#pragma unroll
    for (int j = 0; j < 9; j++) {
        __nv_bfloat16 h, l; wsplit(v[j], h, l);
        sh[wl][lane * 9 + j] = h; sl[wl][lane * 9 + j] = l;
    }
    __syncwarp();
    int span = KP - i0 * 9; if (span > 288) span = 288;
    int n4 = span >> 3;
    const uint4* s0 = (const uint4*)sh[wl];
    const uint4* s1 = (const uint4*)sl[wl];
    uint4* d0 = (uint4*)(A + (size_t)row * KP + i0 * 9);
    uint4* d1 = (uint4*)(A + PS + (size_t)row * KP + i0 * 9);
    for (int idx = lane; idx < n4; idx += 32) { d0[idx] = s0[idx]; d1[idx] = s1[idx]; }
}

__global__ void __launch_bounds__(256)
expW(const float* __restrict__ BW, const float* __restrict__ SW,
     const float* __restrict__ SC, int OUT, int IN, int KP, int CPR,
     __nv_bfloat16* __restrict__ B, size_t PS, int nwarps) {
    __shared__ __align__(16) __nv_bfloat16 sh[8][288];
    __shared__ __align__(16) __nv_bfloat16 sl[8][288];
    int wl = threadIdx.x >> 5, lane = threadIdx.x & 31;
    int w = blockIdx.x * 8 + wl;
    if (w >= nwarps) return;
    int o = w / CPR, ic = w - o * CPR;
    int i0 = ic * 32, i = i0 + lane;
    float v[9];
    if (i < IN && o < OUT) {
        size_t oi = (size_t)o * IN + i;
        float s = SC[oi];
        v[0] = BW[oi];
        const float* sw = SW + oi * 8;
#pragma unroll
        for (int j = 0; j < 8; j++) v[1 + j] = sw[j] * s;
    } else {
#pragma unroll
        for (int j = 0; j < 9; j++) v[j] = 0.0f;
    }
#pragma unroll
    for (int j = 0; j < 9; j++) {
        __nv_bfloat16 h, l; wsplit(v[j], h, l);
        sh[wl][lane * 9 + j] = h; sl[wl][lane * 9 + j] = l;
    }
    __syncwarp();
    int span = KP - i0 * 9; if (span > 288) span = 288;
    int n4 = span >> 3;
    const uint4* s0 = (const uint4*)sh[wl];
    const uint4* s1 = (const uint4*)sl[wl];
    uint4* d0 = (uint4*)(B + (size_t)o * KP + i0 * 9);
    uint4* d1 = (uint4*)(B + PS + (size_t)o * KP + i0 * 9);
    for (int idx = lane; idx < n4; idx += 32) { d0[idx] = s0[idx]; d1[idx] = s1[idx]; }
}

// ------------------------------------------------------------- MMA GEMM
// D[M][Nld] (fp32) = A @ B^T. A: [M][KP] bf16 k-contig, hi plane + lo at +APS.
// B: [N][KP] likewise. fp32 accuracy via 3-pass hi/lo split.
// CTA: BM x BN, 256 threads (8 warps, 2m x 4n), BK=32, STAGES-deep cp.async.
template <int BM, int BN, int STAGES, int MINCTA>
__global__ void __launch_bounds__(256, MINCTA)
gemm_mma(const __nv_bfloat16* __restrict__ A, size_t APS,
         const __nv_bfloat16* __restrict__ B, size_t BPS,
         float* __restrict__ C, int Nld, int KP, int KITERS) {
    constexpr int WM = BM / 2;            // 64
    constexpr int WN = BN / 4;            // 32 | 64
    constexpr int MT = WM / 16;           // 4
    constexpr int NT = WN / 8;            // 4 | 8
    constexpr int LDS = 80;               // smem bytes/row (32 bf16 + 8 pad)
    constexpr int SA = BM * LDS;
    constexpr int SB = BN * LDS;
    constexpr int STAGE = 2 * SA + 2 * SB;
    constexpr int NCHK = (BM + BN) * 8 / 256;

    extern __shared__ __align__(16) char smc[];
    const uint32_t sbase = smem_u32(smc);
    const int tid = threadIdx.x;
    const int lane = tid & 31, wid = tid >> 5;
    const int wm = wid >> 2, wn = wid & 3;
    const int row0 = blockIdx.y * BM, col0 = blockIdx.x * BN;

    const char* baseA = (const char*)(A + (size_t)row0 * KP);
    const char* baseB = (const char*)(B + (size_t)col0 * KP);

    // plan recomputed per load (A/B branch resolves at compile time per j)
    auto load = [&](int stg, int it) {
        uint32_t sb = sbase + stg * STAGE;
        uint32_t ko = (uint32_t)it * 64;   // bytes (32 bf16)
#pragma unroll
        for (int j = 0; j < NCHK; j++) {
            int id = tid + 256 * j;
            if (id < BM * 8) {
                int p = id / (BM * 4), rid = id - p * BM * 4;
                int r = rid >> 2, c = rid & 3;
                cp16(sb + p * SA + r * LDS + c * 16,
                     baseA + (size_t)p * APS * 2 + (size_t)r * KP * 2 + c * 16 + ko);
            } else {
                int id2 = id - BM * 8;
                int p = id2 / (BN * 4), rid = id2 - p * BN * 4;
                int r = rid >> 2, c = rid & 3;
                cp16(sb + 2 * SA + p * SB + r * LDS + c * 16,
                     baseB + (size_t)p * BPS * 2 + (size_t)r * KP * 2 + c * 16 + ko);
            }
        }
        asm volatile("cp.async.commit_group;" ::: "memory");
    };

    // ldmatrix lane offsets within a stage
    uint32_t offA[MT], offB[NT / 2];
#pragma unroll
    for (int mt = 0; mt < MT; mt++)
        offA[mt] = (uint32_t)((wm * WM + mt * 16 + (lane & 15)) * LDS + ((lane >> 4) * 16));
#pragma unroll
    for (int np = 0; np < NT / 2; np++)
        offB[np] = (uint32_t)(2 * SA +
                   (wn * WN + np * 16 + ((lane >> 4) * 8) + (lane & 7)) * LDS +
                   (((lane >> 3) & 1) * 16));

    float acc[MT][NT][4];
#pragma unroll
    for (int i = 0; i < MT; i++)
#pragma unroll
        for (int j = 0; j < NT; j++)
#pragma unroll
            for (int k = 0; k < 4; k++) acc[i][j][k] = 0.0f;

#pragma unroll
    for (int p = 0; p < STAGES - 1; p++) load(p, p);

    for (int it = 0; it < KITERS; it++) {
        const int stg = it % STAGES;
        if (STAGES >= 3 && it + 1 < KITERS)
            asm volatile("cp.async.wait_group 1;" ::: "memory");
        else
            asm volatile("cp.async.wait_group 0;" ::: "memory");
        __syncthreads();
        if (it + STAGES - 1 < KITERS) load((it + STAGES - 1) % STAGES, it + STAGES - 1);

        const uint32_t sb = sbase + stg * STAGE;
#pragma unroll
        for (int s = 0; s < 2; s++) {
            uint32_t ah[MT][4], al[MT][4];
#pragma unroll
            for (int mt = 0; mt < MT; mt++) {
                uint32_t a0 = sb + offA[mt] + s * 32;
                ldm_x4(a0, ah[mt][0], ah[mt][1], ah[mt][2], ah[mt][3]);
                ldm_x4(a0 + SA, al[mt][0], al[mt][1], al[mt][2], al[mt][3]);
            }
#pragma unroll
            for (int np = 0; np < NT / 2; np++) {
                uint32_t bh[2][2], bl[2][2];
                uint32_t b0 = sb + offB[np] + s * 32;
                ldm_x4(b0, bh[0][0], bh[0][1], bh[1][0], bh[1][1]);
                ldm_x4(b0 + SB, bl[0][0], bl[0][1], bl[1][0], bl[1][1]);
#pragma unroll
                for (int q = 0; q < 2; q++) {
                    int nt = 2 * np + q;
#pragma unroll
                    for (int mt = 0; mt < MT; mt++) {
                        mma16816(acc[mt][nt], ah[mt], bh[q]);
                        mma16816(acc[mt][nt], ah[mt], bl[q]);
                        mma16816(acc[mt][nt], al[mt], bh[q]);
                    }
                }
            }
        }
    }

    // epilogue
#pragma unroll
    for (int mt = 0; mt < MT; mt++)
#pragma unroll
        for (int nt = 0; nt < NT; nt++) {
            int r = row0 + wm * WM + mt * 16 + (lane >> 2);
            int c = col0 + wn * WN + nt * 8 + ((lane & 3) << 1);
            *(float2*)&C[(size_t)r * Nld + c] = make_float2(acc[mt][nt][0], acc[mt][nt][1]);
            *(float2*)&C[(size_t)(r + 8) * Nld + c] = make_float2(acc[mt][nt][2], acc[mt][nt][3]);
        }
}

// ---------------------------------------------------------------------------
extern "C" void kernel_launch(void* const* d_in, const int* in_sizes, int n_in,
                              void* d_out, int out_size) {
    const float* x   = (const float*)d_in[0];
    const float* bw1 = (const float*)d_in[1];
    const float* sw1 = (const float*)d_in[2];
    const float* sc1 = (const float*)d_in[3];
    const float* bw2 = (const float*)d_in[4];
    const float* sw2 = (const float*)d_in[5];
    const float* sc2 = (const float*)d_in[6];
    float* out = (float*)d_out;

    __nv_bfloat16 *A1, *B1, *A2, *B2;
    float* H;
    cudaGetSymbolAddress((void**)&A1, g_A1);
    cudaGetSymbolAddress((void**)&B1, g_B1);
    cudaGetSymbolAddress((void**)&H,  g_H);
    cudaGetSymbolAddress((void**)&A2, g_A2);
    cudaGetSymbolAddress((void**)&B2, g_B2);

    const size_t PA1 = (size_t)MROWS * KP1, PB1 = (size_t)NPAD1 * KP1;
    const size_t PA2 = (size_t)MROWS * KP2, PB2 = (size_t)OUT2 * KP2;

    const int SM1 = 3 * (2 * 128 * 80 + 2 * 256 * 80);   // 184320, 1 CTA/SM
    const int SM2 = 2 * (2 * 128 * 80 + 2 * 128 * 80);   //  81920, 2 CTA/SM
    cudaFuncSetAttribute((const void*)gemm_mma<128, 256, 3, 1>,
                         cudaFuncAttributeMaxDynamicSharedMemorySize, SM1);
    cudaFuncSetAttribute((const void*)gemm_mma<128, 128, 2, 2>,
                         cudaFuncAttributeMaxDynamicSharedMemorySize, SM2);

    // -------- Layer 1 --------
    {
        int cpr = (IN1 + 31) / 32;                        // 16
        int nw = MROWS * cpr;
        expA<<<(nw + 7) / 8, 256>>>(x, IN1, IN1, KP1, cpr, A1, PA1, nw);
        int nww = NPAD1 * cpr;
        expW<<<(nww + 7) / 8, 256>>>(bw1, sw1, sc1, OUT1, IN1, KP1, cpr, B1, PB1, nww);
        gemm_mma<128, 256, 3, 1><<<dim3(NPAD1 / 256, MROWS / 128), 256, SM1>>>(
            A1, PA1, B1, PB1, H, NPAD1, KP1, KP1 / 32);
    }
    // -------- Layer 2 --------
    {
        int cpr = (IN2 + 31) / 32;                        // 65
        int nw = MROWS * cpr;
        expA<<<(nw + 7) / 8, 256>>>(H, NPAD1, IN2, KP2, cpr, A2, PA2, nw);
        int nww = OUT2 * cpr;
        expW<<<(nww + 7) / 8, 256>>>(bw2, sw2, sc2, OUT2, IN2, KP2, cpr, B2, PB2, nww);
        gemm_mma<128, 128, 2, 2><<<dim3(OUT2 / 128, MROWS / 128), 256, SM2>>>(
            A2, PA2, B2, PB2, out, OUT2, KP2, KP2 / 32);
    }
}

// round 9
// speedup vs baseline: 2.6980x; 1.0497x over previous
#include <cuda_runtime.h>
#include <cuda_bf16.h>
#include <cstdint>

#define MROWS 4096
#define IN1   512
#define OUT1  2049
#define NPAD1 2304
#define KP1   4608          // IN1*9, 144 chunks of 32
#define IN2   2049
#define OUT2  512
#define KR2   18441         // IN2*9
#define KP2   18496         // padded, 578... chunks of 32 = 578? (18496/32 = 578)

__device__ __align__(128) __nv_bfloat16 g_A1[2ull * MROWS * KP1];
__device__ __align__(128) __nv_bfloat16 g_B1[2ull * NPAD1 * KP1];
__device__ __align__(128) float         g_H [(size_t)MROWS * NPAD1];
__device__ __align__(128) __nv_bfloat16 g_A2[2ull * MROWS * KP2];
__device__ __align__(128) __nv_bfloat16 g_B2[2ull * OUT2 * KP2];
__device__ __align__(128) float         g_P [2ull * MROWS * OUT2];   // split-K partials

// ------------------------------------------------------------- helpers
__device__ __forceinline__ uint32_t smem_u32(const void* p) {
    uint32_t a;
    asm("{ .reg .u64 t; cvta.to.shared.u64 t, %1; cvt.u32.u64 %0, t; }" : "=r"(a) : "l"(p));
    return a;
}
__device__ __forceinline__ void cp16(uint32_t dst, const void* src) {
    asm volatile("cp.async.cg.shared.global [%0], [%1], 16;" :: "r"(dst), "l"(src) : "memory");
}
__device__ __forceinline__ void ldm_x4(uint32_t a, uint32_t& r0, uint32_t& r1,
                                       uint32_t& r2, uint32_t& r3) {
    asm volatile("ldmatrix.sync.aligned.m8n8.x4.shared.b16 {%0,%1,%2,%3}, [%4];"
                 : "=r"(r0), "=r"(r1), "=r"(r2), "=r"(r3) : "r"(a));
}
__device__ __forceinline__ void mma16816(float* d, const uint32_t* a, const uint32_t* b) {
    asm volatile(
        "mma.sync.aligned.m16n8k16.row.col.f32.bf16.bf16.f32 "
        "{%0,%1,%2,%3}, {%4,%5,%6,%7}, {%8,%9}, {%0,%1,%2,%3};"
        : "+f"(d[0]), "+f"(d[1]), "+f"(d[2]), "+f"(d[3])
        : "r"(a[0]), "r"(a[1]), "r"(a[2]), "r"(a[3]), "r"(b[0]), "r"(b[1]));
}

// ------------------------------------------------------------- expansion math
__device__ __forceinline__ void expand9(float x, float v[9]) {
#pragma unroll
    for (int j = 0; j < 9; j++) v[j] = 0.0f;
    v[0] = x / (1.0f + __expf(-x));                       // SiLU
    if (x >= -2.2f && x < 2.2f) {                         // uniform cubic B-spline
        float xm = (x + 2.2f) * 2.5f;
        float fm = floorf(xm);
        int s = (int)fm;
        float u = xm - fm, u2 = u * u, u3 = u2 * u, w = 1.0f - u;
        float nn[4];
        nn[0] = w * w * w * (1.0f / 6.0f);
        nn[1] = fmaf(u3, 0.5f, fmaf(u2, -1.0f, 2.0f / 3.0f));
        nn[2] = fmaf(u3, -0.5f, fmaf(u2, 0.5f, fmaf(u, 0.5f, 1.0f / 6.0f)));
        nn[3] = u3 * (1.0f / 6.0f);
#pragma unroll
        for (int d = 0; d < 4; d++) {
            int t = s - 3 + d;
            if ((unsigned)t < 8u) v[1 + t] = nn[d];
        }
    }
}
__device__ __forceinline__ void wsplit(float f, __nv_bfloat16& h, __nv_bfloat16& l) {
    h = __float2bfloat16(f);                              // rn
    l = __float2bfloat16(f - __bfloat162float(h));
}

// ------------------------------------------------------------- expansion kernels
__global__ void __launch_bounds__(256)
expA(const float* __restrict__ X, int ldx, int IN, int KP, int CPR,
     __nv_bfloat16* __restrict__ A, size_t PS, int nwarps) {
    __shared__ __align__(16) __nv_bfloat16 sh[8][288];
    __shared__ __align__(16) __nv_bfloat16 sl[8][288];
    int wl = threadIdx.x >> 5, lane = threadIdx.x & 31;
    int w = blockIdx.x * 8 + wl;
    if (w >= nwarps) return;
    int row = w / CPR, ic = w - row * CPR;
    int i0 = ic * 32, i = i0 + lane;
    float v[9];
    if (i < IN) expand9(X[(size_t)row * ldx + i], v);
    else {
#pragma unroll
        for (int j = 0; j < 9; j++) v[j] = 0.0f;
    }
#pragma unroll
    for (int j = 0; j < 9; j++) {
        __nv_bfloat16 h, l; wsplit(v[j], h, l);
        sh[wl][lane * 9 + j] = h; sl[wl][lane * 9 + j] = l;
    }
    __syncwarp();
    int span = KP - i0 * 9; if (span > 288) span = 288;
    int n4 = span >> 3;
    const uint4* s0 = (const uint4*)sh[wl];
    const uint4* s1 = (const uint4*)sl[wl];
    uint4* d0 = (uint4*)(A + (size_t)row * KP + i0 * 9);
    uint4* d1 = (uint4*)(A + PS + (size_t)row * KP + i0 * 9);
    for (int idx = lane; idx < n4; idx += 32) { d0[idx] = s0[idx]; d1[idx] = s1[idx]; }
}

__global__ void __launch_bounds__(256)
expW(const float* __restrict__ BW, const float* __restrict__ SW,
     const float* __restrict__ SC, int OUT, int IN, int KP, int CPR,
     __nv_bfloat16* __restrict__ B, size_t PS, int nwarps) {
    __shared__ __align__(16) __nv_bfloat16 sh[8][288];
    __shared__ __align__(16) __nv_bfloat16 sl[8][288];
    int wl = threadIdx.x >> 5, lane = threadIdx.x & 31;
    int w = blockIdx.x * 8 + wl;
    if (w >= nwarps) return;
    int o = w / CPR, ic = w - o * CPR;
    int i0 = ic * 32, i = i0 + lane;
    float v[9];
    if (i < IN && o < OUT) {
        size_t oi = (size_t)o * IN + i;
        float s = SC[oi];
        v[0] = BW[oi];
        const float* sw = SW + oi * 8;
#pragma unroll
        for (int j = 0; j < 8; j++) v[1 + j] = sw[j] * s;
    } else {
#pragma unroll
        for (int j = 0; j < 9; j++) v[j] = 0.0f;
    }
#pragma unroll
    for (int j = 0; j < 9; j++) {
        __nv_bfloat16 h, l; wsplit(v[j], h, l);
        sh[wl][lane * 9 + j] = h; sl[wl][lane * 9 + j] = l;
    }
    __syncwarp();
    int span = KP - i0 * 9; if (span > 288) span = 288;
    int n4 = span >> 3;
    const uint4* s0 = (const uint4*)sh[wl];
    const uint4* s1 = (const uint4*)sl[wl];
    uint4* d0 = (uint4*)(B + (size_t)o * KP + i0 * 9);
    uint4* d1 = (uint4*)(B + PS + (size_t)o * KP + i0 * 9);
    for (int idx = lane; idx < n4; idx += 32) { d0[idx] = s0[idx]; d1[idx] = s1[idx]; }
}

// split-K reduce: out = P[0] + P[1], float4 vectorized
__global__ void __launch_bounds__(256)
addP(const float* __restrict__ P, size_t plane, float* __restrict__ out, int n4) {
    int t = blockIdx.x * blockDim.x + threadIdx.x;
    if (t >= n4) return;
    float4 a = ((const float4*)P)[t];
    float4 b = ((const float4*)(P + plane))[t];
    ((float4*)out)[t] = make_float4(a.x + b.x, a.y + b.y, a.z + b.z, a.w + b.w);
}

// ------------------------------------------------------------- MMA GEMM
// D[M][Nld] (fp32) = A @ B^T over K chunk range [z*KSPLIT, min((z+1)*KSPLIT, KTOT)).
// A: [M][KP] bf16 k-contig, hi plane + lo at +APS. B: [N][KP] likewise.
// fp32 accuracy via 3-pass hi/lo split. Output plane selected by blockIdx.z.
// CTA: BM x BN, 256 threads (8 warps, 2m x 4n), BK=32, STAGES-deep cp.async.
template <int BM, int BN, int STAGES>
__global__ void __launch_bounds__(256, 1)
gemm_mma(const __nv_bfloat16* __restrict__ A, size_t APS,
         const __nv_bfloat16* __restrict__ B, size_t BPS,
         float* __restrict__ C, int Nld, int KP,
         int KTOT, int KSPLIT, size_t zplane) {
    constexpr int WM = BM / 2;            // 64
    constexpr int WN = BN / 4;            // 64
    constexpr int MT = WM / 16;           // 4
    constexpr int NT = WN / 8;            // 8
    constexpr int LDS = 80;               // smem bytes/row (32 bf16 + 8 pad)
    constexpr int SA = BM * LDS;
    constexpr int SB = BN * LDS;
    constexpr int STAGE = 2 * SA + 2 * SB;
    constexpr int NCHK = (BM + BN) * 8 / 256;

    extern __shared__ __align__(16) char smc[];
    const uint32_t sbase = smem_u32(smc);
    const int tid = threadIdx.x;
    const int lane = tid & 31, wid = tid >> 5;
    const int wm = wid >> 2, wn = wid & 3;
    const int row0 = blockIdx.y * BM, col0 = blockIdx.x * BN;

    const int kstart = blockIdx.z * KSPLIT;
    int kit = KTOT - kstart; if (kit > KSPLIT) kit = KSPLIT;
    float* Cz = C + blockIdx.z * zplane;

    const char* baseA = (const char*)(A + (size_t)row0 * KP);
    const char* baseB = (const char*)(B + (size_t)col0 * KP);

    auto load = [&](int stg, int it) {
        uint32_t sb = sbase + stg * STAGE;
        uint32_t ko = (uint32_t)(kstart + it) * 64;   // bytes (32 bf16)
#pragma unroll
        for (int j = 0; j < NCHK; j++) {
            int id = tid + 256 * j;
            if (id < BM * 8) {
                int p = id / (BM * 4), rid = id - p * BM * 4;
                int r = rid >> 2, c = rid & 3;
                cp16(sb + p * SA + r * LDS + c * 16,
                     baseA + (size_t)p * APS * 2 + (size_t)r * KP * 2 + c * 16 + ko);
            } else {
                int id2 = id - BM * 8;
                int p = id2 / (BN * 4), rid = id2 - p * BN * 4;
                int r = rid >> 2, c = rid & 3;
                cp16(sb + 2 * SA + p * SB + r * LDS + c * 16,
                     baseB + (size_t)p * BPS * 2 + (size_t)r * KP * 2 + c * 16 + ko);
            }
        }
        asm volatile("cp.async.commit_group;" ::: "memory");
    };

    // ldmatrix lane offsets within a stage
    uint32_t offA[MT], offB[NT / 2];
#pragma unroll
    for (int mt = 0; mt < MT; mt++)
        offA[mt] = (uint32_t)((wm * WM + mt * 16 + (lane & 15)) * LDS + ((lane >> 4) * 16));
#pragma unroll
    for (int np = 0; np < NT / 2; np++)
        offB[np] = (uint32_t)(2 * SA +
                   (wn * WN + np * 16 + ((lane >> 4) * 8) + (lane & 7)) * LDS +
                   (((lane >> 3) & 1) * 16));

    float acc[MT][NT][4];
#pragma unroll
    for (int i = 0; i < MT; i++)
#pragma unroll
        for (int j = 0; j < NT; j++)
#pragma unroll
            for (int k = 0; k < 4; k++) acc[i][j][k] = 0.0f;

#pragma unroll
    for (int p = 0; p < STAGES - 1; p++) load(p, p);

    for (int it = 0; it < kit; it++) {
        const int stg = it % STAGES;
        if (STAGES >= 3 && it + 1 < kit)
            asm volatile("cp.async.wait_group 1;" ::: "memory");
        else
            asm volatile("cp.async.wait_group 0;" ::: "memory");
        __syncthreads();
        if (it + STAGES - 1 < kit) load((it + STAGES - 1) % STAGES, it + STAGES - 1);

        const uint32_t sb = sbase + stg * STAGE;
#pragma unroll
        for (int s = 0; s < 2; s++) {
            uint32_t ah[MT][4], al[MT][4];
#pragma unroll
            for (int mt = 0; mt < MT; mt++) {
                uint32_t a0 = sb + offA[mt] + s * 32;
                ldm_x4(a0, ah[mt][0], ah[mt][1], ah[mt][2], ah[mt][3]);
                ldm_x4(a0 + SA, al[mt][0], al[mt][1], al[mt][2], al[mt][3]);
            }
#pragma unroll
            for (int np = 0; np < NT / 2; np++) {
                uint32_t bh[2][2], bl[2][2];
                uint32_t b0 = sb + offB[np] + s * 32;
                ldm_x4(b0, bh[0][0], bh[0][1], bh[1][0], bh[1][1]);
                ldm_x4(b0 + SB, bl[0][0], bl[0][1], bl[1][0], bl[1][1]);
#pragma unroll
                for (int q = 0; q < 2; q++) {
                    int nt = 2 * np + q;
#pragma unroll
                    for (int mt = 0; mt < MT; mt++) {
                        mma16816(acc[mt][nt], ah[mt], bh[q]);
                        mma16816(acc[mt][nt], ah[mt], bl[q]);
                        mma16816(acc[mt][nt], al[mt], bh[q]);
                    }
                }
            }
        }
    }

    // epilogue
#pragma unroll
    for (int mt = 0; mt < MT; mt++)
#pragma unroll
        for (int nt = 0; nt < NT; nt++) {
            int r = row0 + wm * WM + mt * 16 + (lane >> 2);
            int c = col0 + wn * WN + nt * 8 + ((lane & 3) << 1);
            *(float2*)&Cz[(size_t)r * Nld + c] = make_float2(acc[mt][nt][0], acc[mt][nt][1]);
            *(float2*)&Cz[(size_t)(r + 8) * Nld + c] = make_float2(acc[mt][nt][2], acc[mt][nt][3]);
        }
}

// ---------------------------------------------------------------------------
extern "C" void kernel_launch(void* const* d_in, const int* in_sizes, int n_in,
                              void* d_out, int out_size) {
    const float* x   = (const float*)d_in[0];
    const float* bw1 = (const float*)d_in[1];
    const float* sw1 = (const float*)d_in[2];
    const float* sc1 = (const float*)d_in[3];
    const float* bw2 = (const float*)d_in[4];
    const float* sw2 = (const float*)d_in[5];
    const float* sc2 = (const float*)d_in[6];
    float* out = (float*)d_out;

    __nv_bfloat16 *A1, *B1, *A2, *B2;
    float *H, *P;
    cudaGetSymbolAddress((void**)&A1, g_A1);
    cudaGetSymbolAddress((void**)&B1, g_B1);
    cudaGetSymbolAddress((void**)&H,  g_H);
    cudaGetSymbolAddress((void**)&A2, g_A2);
    cudaGetSymbolAddress((void**)&B2, g_B2);
    cudaGetSymbolAddress((void**)&P,  g_P);

    const size_t PA1 = (size_t)MROWS * KP1, PB1 = (size_t)NPAD1 * KP1;
    const size_t PA2 = (size_t)MROWS * KP2, PB2 = (size_t)OUT2 * KP2;
    const size_t ZPL = (size_t)MROWS * OUT2;

    const int SM1 = 3 * (2 * 128 * 80 + 2 * 256 * 80);   // 184320, 1 CTA/SM
    cudaFuncSetAttribute((const void*)gemm_mma<128, 256, 3>,
                         cudaFuncAttributeMaxDynamicSharedMemorySize, SM1);

    // -------- Layer 1 --------
    {
        int cpr = (IN1 + 31) / 32;                        // 16
        int nw = MROWS * cpr;
        expA<<<(nw + 7) / 8, 256>>>(x, IN1, IN1, KP1, cpr, A1, PA1, nw);
        int nww = NPAD1 * cpr;
        expW<<<(nww + 7) / 8, 256>>>(bw1, sw1, sc1, OUT1, IN1, KP1, cpr, B1, PB1, nww);
        gemm_mma<128, 256, 3><<<dim3(NPAD1 / 256, MROWS / 128, 1), 256, SM1>>>(
            A1, PA1, B1, PB1, H, NPAD1, KP1, KP1 / 32, KP1 / 32, 0);
    }
    // -------- Layer 2 (split-K = 2) --------
    {
        int cpr = (IN2 + 31) / 32;                        // 65
        int nw = MROWS * cpr;
        expA<<<(nw + 7) / 8, 256>>>(H, NPAD1, IN2, KP2, cpr, A2, PA2, nw);
        int nww = OUT2 * cpr;
        expW<<<(nww + 7) / 8, 256>>>(bw2, sw2, sc2, OUT2, IN2, KP2, cpr, B2, PB2, nww);
        int ktot = KP2 / 32;                              // 578
        int ksplit = (ktot + 1) / 2;                      // 289
        gemm_mma<128, 256, 3><<<dim3(OUT2 / 256, MROWS / 128, 2), 256, SM1>>>(
            A2, PA2, B2, PB2, P, OUT2, KP2, ktot, ksplit, ZPL);
        int n4 = (MROWS * OUT2) / 4;
        addP<<<(n4 + 255) / 256, 256>>>(P, ZPL, out, n4);
    }
}

// round 10
// speedup vs baseline: 2.9360x; 1.0882x over previous
#include <cuda_runtime.h>
#include <cuda_bf16.h>
#include <cstdint>

#define MROWS 4096
#define IN1   512
#define OUT1  2049
#define NGEMM1 2048         // GEMM covers cols 0..2047; col 2048 via fp32 GEMV
#define NPAD1 2304          // H row stride (unchanged layout)
#define KP1   4608          // IN1*9 = 72 chunks of 64
#define IN2   2049
#define OUT2  512
#define KR2   18441         // IN2*9
#define KP2   18496         // 289 chunks of 64

__device__ __align__(128) __nv_bfloat16 g_A1[2ull * MROWS * KP1];
__device__ __align__(128) __nv_bfloat16 g_B1[2ull * NGEMM1 * KP1];
__device__ __align__(128) float         g_H [(size_t)MROWS * NPAD1];
__device__ __align__(128) __nv_bfloat16 g_A2[2ull * MROWS * KP2];
__device__ __align__(128) __nv_bfloat16 g_B2[2ull * OUT2 * KP2];
__device__ __align__(128) float         g_P [2ull * MROWS * OUT2];   // split-K partials

// ------------------------------------------------------------- helpers
__device__ __forceinline__ uint32_t smem_u32(const void* p) {
    uint32_t a;
    asm("{ .reg .u64 t; cvta.to.shared.u64 t, %1; cvt.u32.u64 %0, t; }" : "=r"(a) : "l"(p));
    return a;
}
__device__ __forceinline__ void cp16(uint32_t dst, const void* src) {
    asm volatile("cp.async.cg.shared.global [%0], [%1], 16;" :: "r"(dst), "l"(src) : "memory");
}
__device__ __forceinline__ void ldm_x4(uint32_t a, uint32_t& r0, uint32_t& r1,
                                       uint32_t& r2, uint32_t& r3) {
    asm volatile("ldmatrix.sync.aligned.m8n8.x4.shared.b16 {%0,%1,%2,%3}, [%4];"
                 : "=r"(r0), "=r"(r1), "=r"(r2), "=r"(r3) : "r"(a));
}
__device__ __forceinline__ void mma16816(float* d, const uint32_t* a, const uint32_t* b) {
    asm volatile(
        "mma.sync.aligned.m16n8k16.row.col.f32.bf16.bf16.f32 "
        "{%0,%1,%2,%3}, {%4,%5,%6,%7}, {%8,%9}, {%0,%1,%2,%3};"
        : "+f"(d[0]), "+f"(d[1]), "+f"(d[2]), "+f"(d[3])
        : "r"(a[0]), "r"(a[1]), "r"(a[2]), "r"(a[3]), "r"(b[0]), "r"(b[1]));
}

// ------------------------------------------------------------- expansion math
__device__ __forceinline__ void expand9(float x, float v[9]) {
#pragma unroll
    for (int j = 0; j < 9; j++) v[j] = 0.0f;
    v[0] = x / (1.0f + __expf(-x));                       // SiLU
    if (x >= -2.2f && x < 2.2f) {                         // uniform cubic B-spline
        float xm = (x + 2.2f) * 2.5f;
        float fm = floorf(xm);
        int s = (int)fm;
        float u = xm - fm, u2 = u * u, u3 = u2 * u, w = 1.0f - u;
        float nn[4];
        nn[0] = w * w * w * (1.0f / 6.0f);
        nn[1] = fmaf(u3, 0.5f, fmaf(u2, -1.0f, 2.0f / 3.0f));
        nn[2] = fmaf(u3, -0.5f, fmaf(u2, 0.5f, fmaf(u, 0.5f, 1.0f / 6.0f)));
        nn[3] = u3 * (1.0f / 6.0f);
#pragma unroll
        for (int d = 0; d < 4; d++) {
            int t = s - 3 + d;
            if ((unsigned)t < 8u) v[1 + t] = nn[d];
        }
    }
}
__device__ __forceinline__ void wsplit(float f, __nv_bfloat16& h, __nv_bfloat16& l) {
    h = __float2bfloat16(f);                              // rn
    l = __float2bfloat16(f - __bfloat162float(h));
}

// ------------------------------------------------------------- expansion kernels
__global__ void __launch_bounds__(256)
expA(const float* __restrict__ X, int ldx, int IN, int KP, int CPR,
     __nv_bfloat16* __restrict__ A, size_t PS, int nwarps) {
    __shared__ __align__(16) __nv_bfloat16 sh[8][288];
    __shared__ __align__(16) __nv_bfloat16 sl[8][288];
    int wl = threadIdx.x >> 5, lane = threadIdx.x & 31;
    int w = blockIdx.x * 8 + wl;
    if (w >= nwarps) return;
    int row = w / CPR, ic = w - row * CPR;
    int i0 = ic * 32, i = i0 + lane;
    float v[9];
    if (i < IN) expand9(X[(size_t)row * ldx + i], v);
    else {
#pragma unroll
        for (int j = 0; j < 9; j++) v[j] = 0.0f;
    }
#pragma unroll
    for (int j = 0; j < 9; j++) {
        __nv_bfloat16 h, l; wsplit(v[j], h, l);
        sh[wl][lane * 9 + j] = h; sl[wl][lane * 9 + j] = l;
    }
    __syncwarp();
    int span = KP - i0 * 9; if (span > 288) span = 288;
    int n4 = span >> 3;
    const uint4* s0 = (const uint4*)sh[wl];
    const uint4* s1 = (const uint4*)sl[wl];
    uint4* d0 = (uint4*)(A + (size_t)row * KP + i0 * 9);
    uint4* d1 = (uint4*)(A + PS + (size_t)row * KP + i0 * 9);
    for (int idx = lane; idx < n4; idx += 32) { d0[idx] = s0[idx]; d1[idx] = s1[idx]; }
}

__global__ void __launch_bounds__(256)
expW(const float* __restrict__ BW, const float* __restrict__ SW,
     const float* __restrict__ SC, int OUT, int IN, int KP, int CPR,
     __nv_bfloat16* __restrict__ B, size_t PS, int nwarps) {
    __shared__ __align__(16) __nv_bfloat16 sh[8][288];
    __shared__ __align__(16) __nv_bfloat16 sl[8][288];
    int wl = threadIdx.x >> 5, lane = threadIdx.x & 31;
    int w = blockIdx.x * 8 + wl;
    if (w >= nwarps) return;
    int o = w / CPR, ic = w - o * CPR;
    int i0 = ic * 32, i = i0 + lane;
    float v[9];
    if (i < IN && o < OUT) {
        size_t oi = (size_t)o * IN + i;
        float s = SC[oi];
        v[0] = BW[oi];
        const float* sw = SW + oi * 8;
#pragma unroll
        for (int j = 0; j < 8; j++) v[1 + j] = sw[j] * s;
    } else {
#pragma unroll
        for (int j = 0; j < 9; j++) v[j] = 0.0f;
    }
#pragma unroll
    for (int j = 0; j < 9; j++) {
        __nv_bfloat16 h, l; wsplit(v[j], h, l);
        sh[wl][lane * 9 + j] = h; sl[wl][lane * 9 + j] = l;
    }
    __syncwarp();
    int span = KP - i0 * 9; if (span > 288) span = 288;
    int n4 = span >> 3;
    const uint4* s0 = (const uint4*)sh[wl];
    const uint4* s1 = (const uint4*)sl[wl];
    uint4* d0 = (uint4*)(B + (size_t)o * KP + i0 * 9);
    uint4* d1 = (uint4*)(B + PS + (size_t)o * KP + i0 * 9);
    for (int idx = lane; idx < n4; idx += 32) { d0[idx] = s0[idx]; d1[idx] = s1[idx]; }
}

// fp32 GEMV for layer-1 output column 2048 (exact, one warp per row)
__global__ void __launch_bounds__(256)
gemv_col(const float* __restrict__ X, const float* __restrict__ BW,
         const float* __restrict__ SW, const float* __restrict__ SC,
         float* __restrict__ H) {
    const int col = NGEMM1;                                // 2048
    int w = blockIdx.x * 8 + (threadIdx.x >> 5);
    int lane = threadIdx.x & 31;
    if (w >= MROWS) return;
    const float* xr = X + (size_t)w * IN1;
    float acc = 0.0f;
    for (int i = lane; i < IN1; i += 32) {
        float v[9];
        expand9(xr[i], v);
        size_t oi = (size_t)col * IN1 + i;
        acc = fmaf(v[0], BW[oi], acc);
        float s = SC[oi];
        const float* swp = SW + oi * 8;
#pragma unroll
        for (int j = 0; j < 8; j++) acc = fmaf(v[1 + j] * s, swp[j], acc);
    }
#pragma unroll
    for (int o = 16; o; o >>= 1) acc += __shfl_xor_sync(0xFFFFFFFFu, acc, o);
    if (lane == 0) H[(size_t)w * NPAD1 + col] = acc;
}

// split-K reduce: out = P[0] + P[1], float4 vectorized
__global__ void __launch_bounds__(256)
addP(const float* __restrict__ P, size_t plane, float* __restrict__ out, int n4) {
    int t = blockIdx.x * blockDim.x + threadIdx.x;
    if (t >= n4) return;
    float4 a = ((const float4*)P)[t];
    float4 b = ((const float4*)(P + plane))[t];
    ((float4*)out)[t] = make_float4(a.x + b.x, a.y + b.y, a.z + b.z, a.w + b.w);
}

// ------------------------------------------------------------- MMA GEMM
// D[M][Nld] (fp32) = A @ B^T over K chunk range [z*KSPLIT, min((z+1)*KSPLIT, KTOT)),
// chunks of BK=64. A: [M][KP] bf16 k-contig, hi plane + lo at +APS. B likewise.
// fp32 accuracy via 3-pass hi/lo split. Output plane selected by blockIdx.z.
// CTA: 128 x 256, 256 threads (8 warps, 2m x 4n), 2-stage cp.async.
__global__ void __launch_bounds__(256, 1)
gemm_mma(const __nv_bfloat16* __restrict__ A, size_t APS,
         const __nv_bfloat16* __restrict__ B, size_t BPS,
         float* __restrict__ C, int Nld, int KP,
         int KTOT, int KSPLIT, size_t zplane) {
    constexpr int BM = 128, BN = 256;
    constexpr int WM = 64, WN = 64;
    constexpr int MT = 4, NT = 8;
    constexpr int LDS = 144;              // 64 bf16 (128B) + 16B pad
    constexpr int SA = BM * LDS;          // 18432
    constexpr int SB = BN * LDS;          // 36864
    constexpr int STAGE = 2 * SA + 2 * SB;// 110592
    constexpr int NCHK = (BM + BN) * 16 / 256;  // 24

    extern __shared__ __align__(16) char smc[];
    const uint32_t sbase = smem_u32(smc);
    const int tid = threadIdx.x;
    const int lane = tid & 31, wid = tid >> 5;
    const int wm = wid >> 2, wn = wid & 3;
    const int row0 = blockIdx.y * BM, col0 = blockIdx.x * BN;

    const int kstart = blockIdx.z * KSPLIT;
    int kit = KTOT - kstart; if (kit > KSPLIT) kit = KSPLIT;
    float* Cz = C + blockIdx.z * zplane;

    const char* baseA = (const char*)(A + (size_t)row0 * KP);
    const char* baseB = (const char*)(B + (size_t)col0 * KP);

    auto load = [&](int stg, int it) {
        uint32_t sb = sbase + stg * STAGE;
        uint32_t ko = (uint32_t)(kstart + it) * 128;   // bytes (64 bf16)
#pragma unroll
        for (int j = 0; j < NCHK; j++) {
            int id = tid + 256 * j;
            if (id < BM * 16) {
                int p = id / (BM * 8), rid = id - p * BM * 8;
                int r = rid >> 3, c = rid & 7;
                cp16(sb + p * SA + r * LDS + c * 16,
                     baseA + (size_t)p * APS * 2 + (size_t)r * KP * 2 + c * 16 + ko);
            } else {
                int id2 = id - BM * 16;
                int p = id2 / (BN * 8), rid = id2 - p * BN * 8;
                int r = rid >> 3, c = rid & 7;
                cp16(sb + 2 * SA + p * SB + r * LDS + c * 16,
                     baseB + (size_t)p * BPS * 2 + (size_t)r * KP * 2 + c * 16 + ko);
            }
        }
        asm volatile("cp.async.commit_group;" ::: "memory");
    };

    // ldmatrix lane offsets within a stage
    uint32_t offA[MT], offB[NT / 2];
#pragma unroll
    for (int mt = 0; mt < MT; mt++)
        offA[mt] = (uint32_t)((wm * WM + mt * 16 + (lane & 15)) * LDS + ((lane >> 4) * 16));
#pragma unroll
    for (int np = 0; np < NT / 2; np++)
        offB[np] = (uint32_t)(2 * SA +
                   (wn * WN + np * 16 + ((lane >> 4) * 8) + (lane & 7)) * LDS +
                   (((lane >> 3) & 1) * 16));

    float acc[MT][NT][4];
#pragma unroll
    for (int i = 0; i < MT; i++)
#pragma unroll
        for (int j = 0; j < NT; j++)
#pragma unroll
            for (int k = 0; k < 4; k++) acc[i][j][k] = 0.0f;

    load(0, 0);

    for (int it = 0; it < kit; it++) {
        const int stg = it & 1;
        asm volatile("cp.async.wait_group 0;" ::: "memory");
        __syncthreads();
        if (it + 1 < kit) load(stg ^ 1, it + 1);

        const uint32_t sb = sbase + stg * STAGE;
#pragma unroll
        for (int s = 0; s < 4; s++) {                      // 4 k-steps of 16
            uint32_t ah[MT][4], al[MT][4];
#pragma unroll
            for (int mt = 0; mt < MT; mt++) {
                uint32_t a0 = sb + offA[mt] + s * 32;
                ldm_x4(a0, ah[mt][0], ah[mt][1], ah[mt][2], ah[mt][3]);
                ldm_x4(a0 + SA, al[mt][0], al[mt][1], al[mt][2], al[mt][3]);
            }
#pragma unroll
            for (int np = 0; np < NT / 2; np++) {
                uint32_t bh[2][2], bl[2][2];
                uint32_t b0 = sb + offB[np] + s * 32;
                ldm_x4(b0, bh[0][0], bh[0][1], bh[1][0], bh[1][1]);
                ldm_x4(b0 + SB, bl[0][0], bl[0][1], bl[1][0], bl[1][1]);
#pragma unroll
                for (int q = 0; q < 2; q++) {
                    int nt = 2 * np + q;
#pragma unroll
                    for (int mt = 0; mt < MT; mt++) {
                        mma16816(acc[mt][nt], ah[mt], bh[q]);
                        mma16816(acc[mt][nt], ah[mt], bl[q]);
                        mma16816(acc[mt][nt], al[mt], bh[q]);
                    }
                }
            }
        }
    }

    // epilogue
#pragma unroll
    for (int mt = 0; mt < MT; mt++)
#pragma unroll
        for (int nt = 0; nt < NT; nt++) {
            int r = row0 + wm * WM + mt * 16 + (lane >> 2);
            int c = col0 + wn * WN + nt * 8 + ((lane & 3) << 1);
            *(float2*)&Cz[(size_t)r * Nld + c] = make_float2(acc[mt][nt][0], acc[mt][nt][1]);
            *(float2*)&Cz[(size_t)(r + 8) * Nld + c] = make_float2(acc[mt][nt][2], acc[mt][nt][3]);
        }
}

// ---------------------------------------------------------------------------
extern "C" void kernel_launch(void* const* d_in, const int* in_sizes, int n_in,
                              void* d_out, int out_size) {
    const float* x   = (const float*)d_in[0];
    const float* bw1 = (const float*)d_in[1];
    const float* sw1 = (const float*)d_in[2];
    const float* sc1 = (const float*)d_in[3];
    const float* bw2 = (const float*)d_in[4];
    const float* sw2 = (const float*)d_in[5];
    const float* sc2 = (const float*)d_in[6];
    float* out = (float*)d_out;

    __nv_bfloat16 *A1, *B1, *A2, *B2;
    float *H, *P;
    cudaGetSymbolAddress((void**)&A1, g_A1);
    cudaGetSymbolAddress((void**)&B1, g_B1);
    cudaGetSymbolAddress((void**)&H,  g_H);
    cudaGetSymbolAddress((void**)&A2, g_A2);
    cudaGetSymbolAddress((void**)&B2, g_B2);
    cudaGetSymbolAddress((void**)&P,  g_P);

    const size_t PA1 = (size_t)MROWS * KP1, PB1 = (size_t)NGEMM1 * KP1;
    const size_t PA2 = (size_t)MROWS * KP2, PB2 = (size_t)OUT2 * KP2;
    const size_t ZPL = (size_t)MROWS * OUT2;

    const int SMEM = 2 * (2 * 128 * 144 + 2 * 256 * 144);   // 221184
    cudaFuncSetAttribute((const void*)gemm_mma,
                         cudaFuncAttributeMaxDynamicSharedMemorySize, SMEM);

    // -------- Layer 1 --------
    {
        int cpr = (IN1 + 31) / 32;                        // 16
        int nw = MROWS * cpr;
        expA<<<(nw + 7) / 8, 256>>>(x, IN1, IN1, KP1, cpr, A1, PA1, nw);
        int nww = NGEMM1 * cpr;
        expW<<<(nww + 7) / 8, 256>>>(bw1, sw1, sc1, NGEMM1, IN1, KP1, cpr, B1, PB1, nww);
        gemm_mma<<<dim3(NGEMM1 / 256, MROWS / 128, 1), 256, SMEM>>>(
            A1, PA1, B1, PB1, H, NPAD1, KP1, KP1 / 64, KP1 / 64, 0);
        gemv_col<<<MROWS / 8, 256>>>(x, bw1, sw1, sc1, H);
    }
    // -------- Layer 2 (split-K = 2) --------
    {
        int cpr = (IN2 + 31) / 32;                        // 65
        int nw = MROWS * cpr;
        expA<<<(nw + 7) / 8, 256>>>(H, NPAD1, IN2, KP2, cpr, A2, PA2, nw);
        int nww = OUT2 * cpr;
        expW<<<(nww + 7) / 8, 256>>>(bw2, sw2, sc2, OUT2, IN2, KP2, cpr, B2, PB2, nww);
        int ktot = KP2 / 64;                              // 289
        int ksplit = (ktot + 1) / 2;                      // 145
        gemm_mma<<<dim3(OUT2 / 256, MROWS / 128, 2), 256, SMEM>>>(
            A2, PA2, B2, PB2, P, OUT2, KP2, ktot, ksplit, ZPL);
        int n4 = (MROWS * OUT2) / 4;
        addP<<<(n4 + 255) / 256, 256>>>(P, ZPL, out, n4);
    }
}

// round 11
// speedup vs baseline: 3.4187x; 1.1644x over previous
#include <cuda_runtime.h>
#include <cuda_bf16.h>
#include <cstdint>

#define MROWS 4096
#define IN1   512
#define OUT1  2049
#define NGEMM1 2048         // GEMM cols 0..2047; col 2048 via fp32 GEMV
#define NPAD1 2304          // H row stride
#define KP1   4608          // IN1*9 = 72 chunks of 64
#define NCH1  72
#define IN2   2049
#define OUT2  512
#define KR2   18441
#define KP2   18496         // 289 chunks of 64
#define NCH2  289
#define RW    72            // bf16 per row per chunk (64 real + 8 pad)

// chunk-major staging: [plane][kchunk][row][RW]
#define ACH   ((size_t)MROWS * RW)              // chunk stride (elements)
#define BCH1  ((size_t)NGEMM1 * RW)
#define BCH2  ((size_t)OUT2 * RW)
#define APS1  ((size_t)NCH1 * ACH)
#define BPS1  ((size_t)NCH1 * BCH1)
#define APS2  ((size_t)NCH2 * ACH)
#define BPS2  ((size_t)NCH2 * BCH2)

__device__ __align__(128) __nv_bfloat16 g_A1[2 * APS1];
__device__ __align__(128) __nv_bfloat16 g_B1[2 * BPS1];
__device__ __align__(128) float         g_H [(size_t)MROWS * NPAD1];
__device__ __align__(128) __nv_bfloat16 g_A2[2 * APS2];
__device__ __align__(128) __nv_bfloat16 g_B2[2 * BPS2];
__device__ __align__(128) float         g_P [2ull * MROWS * OUT2];

// ------------------------------------------------------------- helpers
__device__ __forceinline__ uint32_t smem_u32(const void* p) {
    uint32_t a;
    asm("{ .reg .u64 t; cvta.to.shared.u64 t, %1; cvt.u32.u64 %0, t; }" : "=r"(a) : "l"(p));
    return a;
}
__device__ __forceinline__ void mbar_init(uint32_t a, uint32_t c) {
    asm volatile("mbarrier.init.shared.b64 [%0], %1;" :: "r"(a), "r"(c) : "memory");
}
__device__ __forceinline__ void mbar_wait(uint32_t a, uint32_t par) {
    uint32_t done = 0;
    while (!done)
        asm volatile("{\n\t.reg .pred P;\n\t"
            "mbarrier.try_wait.parity.acquire.cta.shared::cta.b64 P, [%1], %2, 0x989680;\n\t"
            "selp.b32 %0, 1, 0, P;\n\t}" : "=r"(done) : "r"(a), "r"(par) : "memory");
}
__device__ __forceinline__ void bulk_g2s(uint32_t dst, const void* src, uint32_t bytes, uint32_t mb) {
    asm volatile("cp.async.bulk.shared::cluster.global.mbarrier::complete_tx::bytes "
                 "[%0], [%1], %2, [%3];"
                 :: "r"(dst), "l"(src), "r"(bytes), "r"(mb) : "memory");
}
__device__ __forceinline__ void ldm_x4(uint32_t a, uint32_t& r0, uint32_t& r1,
                                       uint32_t& r2, uint32_t& r3) {
    asm volatile("ldmatrix.sync.aligned.m8n8.x4.shared.b16 {%0,%1,%2,%3}, [%4];"
                 : "=r"(r0), "=r"(r1), "=r"(r2), "=r"(r3) : "r"(a));
}
__device__ __forceinline__ void mma16816(float* d, const uint32_t* a, const uint32_t* b) {
    asm volatile(
        "mma.sync.aligned.m16n8k16.row.col.f32.bf16.bf16.f32 "
        "{%0,%1,%2,%3}, {%4,%5,%6,%7}, {%8,%9}, {%0,%1,%2,%3};"
        : "+f"(d[0]), "+f"(d[1]), "+f"(d[2]), "+f"(d[3])
        : "r"(a[0]), "r"(a[1]), "r"(a[2]), "r"(a[3]), "r"(b[0]), "r"(b[1]));
}

// ------------------------------------------------------------- expansion math
__device__ __forceinline__ void expand9(float x, float v[9]) {
#pragma unroll
    for (int j = 0; j < 9; j++) v[j] = 0.0f;
    v[0] = x / (1.0f + __expf(-x));                       // SiLU
    if (x >= -2.2f && x < 2.2f) {                         // uniform cubic B-spline
        float xm = (x + 2.2f) * 2.5f;
        float fm = floorf(xm);
        int s = (int)fm;
        float u = xm - fm, u2 = u * u, u3 = u2 * u, w = 1.0f - u;
        float nn[4];
        nn[0] = w * w * w * (1.0f / 6.0f);
        nn[1] = fmaf(u3, 0.5f, fmaf(u2, -1.0f, 2.0f / 3.0f));
        nn[2] = fmaf(u3, -0.5f, fmaf(u2, 0.5f, fmaf(u, 0.5f, 1.0f / 6.0f)));
        nn[3] = u3 * (1.0f / 6.0f);
#pragma unroll
        for (int d = 0; d < 4; d++) {
            int t = s - 3 + d;
            if ((unsigned)t < 8u) v[1 + t] = nn[d];
        }
    }
}
__device__ __forceinline__ void wsplit(float f, __nv_bfloat16& h, __nv_bfloat16& l) {
    h = __float2bfloat16(f);
    l = __float2bfloat16(f - __bfloat162float(h));
}

// write one warp's 288-k span from smem staging into chunk-major layout
__device__ __forceinline__ void store_span(const __nv_bfloat16* sh, const __nv_bfloat16* sl,
                                           __nv_bfloat16* D, size_t PS, size_t CHS,
                                           int row, int k0, int KP, int lane) {
    int span = KP - k0; if (span > 288) span = 288;
    int off = 0;
    while (off < span) {
        int k = k0 + off;
        int ki = k >> 6, kin = k & 63;
        int len = 64 - kin; if (len > span - off) len = span - off;
        __nv_bfloat16* dh = D + (size_t)ki * CHS + (size_t)row * RW + kin;
        const uint4* s0 = (const uint4*)(sh + off);
        const uint4* s1 = (const uint4*)(sl + off);
        int n4 = len >> 3;
        for (int idx = lane; idx < n4; idx += 32) {
            ((uint4*)dh)[idx] = s0[idx];
            ((uint4*)(dh + PS))[idx] = s1[idx];
        }
        off += len;
    }
}

// ------------------------------------------------------------- expansion kernels
__global__ void __launch_bounds__(256)
expA(const float* __restrict__ X, int ldx, int IN, int KP, int CPR,
     __nv_bfloat16* __restrict__ A, size_t PS, size_t CHS, int nwarps) {
    __shared__ __align__(16) __nv_bfloat16 sh[8][288];
    __shared__ __align__(16) __nv_bfloat16 sl[8][288];
    int wl = threadIdx.x >> 5, lane = threadIdx.x & 31;
    int w = blockIdx.x * 8 + wl;
    if (w >= nwarps) return;
    int row = w / CPR, ic = w - row * CPR;
    int i0 = ic * 32, i = i0 + lane;
    float v[9];
    if (i < IN) expand9(X[(size_t)row * ldx + i], v);
    else {
#pragma unroll
        for (int j = 0; j < 9; j++) v[j] = 0.0f;
    }
#pragma unroll
    for (int j = 0; j < 9; j++) {
        __nv_bfloat16 h, l; wsplit(v[j], h, l);
        sh[wl][lane * 9 + j] = h; sl[wl][lane * 9 + j] = l;
    }
    __syncwarp();
    store_span(sh[wl], sl[wl], A, PS, CHS, row, i0 * 9, KP, lane);
}

__global__ void __launch_bounds__(256)
expW(const float* __restrict__ BW, const float* __restrict__ SW,
     const float* __restrict__ SC, int OUT, int IN, int KP, int CPR,
     __nv_bfloat16* __restrict__ B, size_t PS, size_t CHS, int nwarps) {
    __shared__ __align__(16) __nv_bfloat16 sh[8][288];
    __shared__ __align__(16) __nv_bfloat16 sl[8][288];
    int wl = threadIdx.x >> 5, lane = threadIdx.x & 31;
    int w = blockIdx.x * 8 + wl;
    if (w >= nwarps) return;
    int o = w / CPR, ic = w - o * CPR;
    int i0 = ic * 32, i = i0 + lane;
    float v[9];
    if (i < IN && o < OUT) {
        size_t oi = (size_t)o * IN + i;
        float s = SC[oi];
        v[0] = BW[oi];
        const float* sw = SW + oi * 8;
#pragma unroll
        for (int j = 0; j < 8; j++) v[1 + j] = sw[j] * s;
    } else {
#pragma unroll
        for (int j = 0; j < 9; j++) v[j] = 0.0f;
    }
#pragma unroll
    for (int j = 0; j < 9; j++) {
        __nv_bfloat16 h, l; wsplit(v[j], h, l);
        sh[wl][lane * 9 + j] = h; sl[wl][lane * 9 + j] = l;
    }
    __syncwarp();
    store_span(sh[wl], sl[wl], B, PS, CHS, o, i0 * 9, KP, lane);
}

// fp32 GEMV for layer-1 output column 2048 (exact, one warp per row)
__global__ void __launch_bounds__(256)
gemv_col(const float* __restrict__ X, const float* __restrict__ BW,
         const float* __restrict__ SW, const float* __restrict__ SC,
         float* __restrict__ H) {
    const int col = NGEMM1;
    int w = blockIdx.x * 8 + (threadIdx.x >> 5);
    int lane = threadIdx.x & 31;
    if (w >= MROWS) return;
    const float* xr = X + (size_t)w * IN1;
    float acc = 0.0f;
    for (int i = lane; i < IN1; i += 32) {
        float v[9];
        expand9(xr[i], v);
        size_t oi = (size_t)col * IN1 + i;
        acc = fmaf(v[0], BW[oi], acc);
        float s = SC[oi];
        const float* swp = SW + oi * 8;
#pragma unroll
        for (int j = 0; j < 8; j++) acc = fmaf(v[1 + j] * s, swp[j], acc);
    }
#pragma unroll
    for (int o = 16; o; o >>= 1) acc += __shfl_xor_sync(0xFFFFFFFFu, acc, o);
    if (lane == 0) H[(size_t)w * NPAD1 + col] = acc;
}

// split-K reduce
__global__ void __launch_bounds__(256)
addP(const float* __restrict__ P, size_t plane, float* __restrict__ out, int n4) {
    int t = blockIdx.x * blockDim.x + threadIdx.x;
    if (t >= n4) return;
    float4 a = ((const float4*)P)[t];
    float4 b = ((const float4*)(P + plane))[t];
    ((float4*)out)[t] = make_float4(a.x + b.x, a.y + b.y, a.z + b.z, a.w + b.w);
}

// ------------------------------------------------------------- MMA GEMM
// D = A @ B^T, chunk-major inputs: A[ki][m][RW] (hi plane, lo at +APS), B likewise.
// 4 cp.async.bulk per chunk + mbarrier. 3-pass bf16 hi/lo split, fp32 accum.
// CTA 128x256, 8 warps (2m x 4n), 2-stage.
__global__ void __launch_bounds__(256, 1)
gemm_mma(const __nv_bfloat16* __restrict__ A, size_t APS, size_t ACHs,
         const __nv_bfloat16* __restrict__ B, size_t BPS, size_t BCHs,
         float* __restrict__ C, int Nld, int KTOT, int KSPLIT, size_t zplane) {
    constexpr int BM = 128, BN = 256;
    constexpr int WM = 64, WN = 64, MT = 4, NT = 8;
    constexpr int LDS = 144;
    constexpr int SA = BM * LDS;            // 18432
    constexpr int SB = BN * LDS;            // 36864
    constexpr int STAGE = 2 * SA + 2 * SB;  // 110592

    extern __shared__ __align__(128) char smc[];
    __shared__ __align__(8) uint64_t mbar_s[2];
    const uint32_t sbase = smem_u32(smc);
    const uint32_t mb0 = smem_u32(&mbar_s[0]);
    const int tid = threadIdx.x;
    const int lane = tid & 31, wid = tid >> 5;
    const int wm = wid >> 2, wn = wid & 3;
    const int row0 = blockIdx.y * BM, col0 = blockIdx.x * BN;

    const int kstart = blockIdx.z * KSPLIT;
    int kit = KTOT - kstart; if (kit > KSPLIT) kit = KSPLIT;
    float* Cz = C + blockIdx.z * zplane;

    if (tid == 0) { mbar_init(mb0, 1); mbar_init(mb0 + 8, 1); }
    __syncthreads();

    auto issue = [&](int stg, int it) {
        uint32_t mb = mb0 + stg * 8;
        asm volatile("mbarrier.arrive.expect_tx.shared.b64 _, [%0], %1;"
                     :: "r"(mb), "r"((uint32_t)STAGE) : "memory");
        size_t ki = (size_t)(kstart + it);
        uint32_t sb = sbase + stg * STAGE;
        const __nv_bfloat16* ah = A + ki * ACHs + (size_t)row0 * RW;
        const __nv_bfloat16* bh = B + ki * BCHs + (size_t)col0 * RW;
        bulk_g2s(sb,               ah,        SA, mb);
        bulk_g2s(sb + SA,          ah + APS,  SA, mb);
        bulk_g2s(sb + 2 * SA,      bh,        SB, mb);
        bulk_g2s(sb + 2 * SA + SB, bh + BPS,  SB, mb);
    };

    // ldmatrix lane offsets within a stage
    uint32_t offA[MT], offB[NT / 2];
#pragma unroll
    for (int mt = 0; mt < MT; mt++)
        offA[mt] = (uint32_t)((wm * WM + mt * 16 + (lane & 15)) * LDS + ((lane >> 4) * 16));
#pragma unroll
    for (int np = 0; np < NT / 2; np++)
        offB[np] = (uint32_t)(2 * SA +
                   (wn * WN + np * 16 + ((lane >> 4) * 8) + (lane & 7)) * LDS +
                   (((lane >> 3) & 1) * 16));

    float acc[MT][NT][4];
#pragma unroll
    for (int i = 0; i < MT; i++)
#pragma unroll
        for (int j = 0; j < NT; j++)
#pragma unroll
            for (int k = 0; k < 4; k++) acc[i][j][k] = 0.0f;

    if (tid == 0) issue(0, 0);

    for (int it = 0; it < kit; it++) {
        const int stg = it & 1;
        if (it + 1 < kit) {
            __syncthreads();                       // all warps done with buffer stg^1
            if (tid == 0) issue(stg ^ 1, it + 1);
        }
        mbar_wait(mb0 + stg * 8, (it >> 1) & 1);

        const uint32_t sb = sbase + stg * STAGE;
#pragma unroll
        for (int s = 0; s < 4; s++) {              // 4 k-steps of 16
            uint32_t ah[MT][4], al[MT][4];
#pragma unroll
            for (int mt = 0; mt < MT; mt++) {
                uint32_t a0 = sb + offA[mt] + s * 32;
                ldm_x4(a0, ah[mt][0], ah[mt][1], ah[mt][2], ah[mt][3]);
                ldm_x4(a0 + SA, al[mt][0], al[mt][1], al[mt][2], al[mt][3]);
            }
#pragma unroll
            for (int np = 0; np < NT / 2; np++) {
                uint32_t bh[2][2], bl[2][2];
                uint32_t b0 = sb + offB[np] + s * 32;
                ldm_x4(b0, bh[0][0], bh[0][1], bh[1][0], bh[1][1]);
                ldm_x4(b0 + SB, bl[0][0], bl[0][1], bl[1][0], bl[1][1]);
#pragma unroll
                for (int q = 0; q < 2; q++) {
                    int nt = 2 * np + q;
#pragma unroll
                    for (int mt = 0; mt < MT; mt++) {
                        mma16816(acc[mt][nt], ah[mt], bh[q]);
                        mma16816(acc[mt][nt], ah[mt], bl[q]);
                        mma16816(acc[mt][nt], al[mt], bh[q]);
                    }
                }
            }
        }
    }

    // epilogue
#pragma unroll
    for (int mt = 0; mt < MT; mt++)
#pragma unroll
        for (int nt = 0; nt < NT; nt++) {
            int r = row0 + wm * WM + mt * 16 + (lane >> 2);
            int c = col0 + wn * WN + nt * 8 + ((lane & 3) << 1);
            *(float2*)&Cz[(size_t)r * Nld + c] = make_float2(acc[mt][nt][0], acc[mt][nt][1]);
            *(float2*)&Cz[(size_t)(r + 8) * Nld + c] = make_float2(acc[mt][nt][2], acc[mt][nt][3]);
        }
}

// ---------------------------------------------------------------------------
extern "C" void kernel_launch(void* const* d_in, const int* in_sizes, int n_in,
                              void* d_out, int out_size) {
    const float* x   = (const float*)d_in[0];
    const float* bw1 = (const float*)d_in[1];
    const float* sw1 = (const float*)d_in[2];
    const float* sc1 = (const float*)d_in[3];
    const float* bw2 = (const float*)d_in[4];
    const float* sw2 = (const float*)d_in[5];
    const float* sc2 = (const float*)d_in[6];
    float* out = (float*)d_out;

    __nv_bfloat16 *A1, *B1, *A2, *B2;
    float *H, *P;
    cudaGetSymbolAddress((void**)&A1, g_A1);
    cudaGetSymbolAddress((void**)&B1, g_B1);
    cudaGetSymbolAddress((void**)&H,  g_H);
    cudaGetSymbolAddress((void**)&A2, g_A2);
    cudaGetSymbolAddress((void**)&B2, g_B2);
    cudaGetSymbolAddress((void**)&P,  g_P);

    const size_t ZPL = (size_t)MROWS * OUT2;
    const int SMEM = 2 * (2 * 128 * 144 + 2 * 256 * 144);   // 221184
    cudaFuncSetAttribute((const void*)gemm_mma,
                         cudaFuncAttributeMaxDynamicSharedMemorySize, SMEM);

    // -------- Layer 1 --------
    {
        int cpr = (IN1 + 31) / 32;                        // 16
        int nw = MROWS * cpr;
        expA<<<(nw + 7) / 8, 256>>>(x, IN1, IN1, KP1, cpr, A1, APS1, ACH, nw);
        int nww = NGEMM1 * cpr;
        expW<<<(nww + 7) / 8, 256>>>(bw1, sw1, sc1, NGEMM1, IN1, KP1, cpr, B1, BPS1, BCH1, nww);
        gemm_mma<<<dim3(NGEMM1 / 256, MROWS / 128, 1), 256, SMEM>>>(
            A1, APS1, ACH, B1, BPS1, BCH1, H, NPAD1, NCH1, NCH1, 0);
        gemv_col<<<MROWS / 8, 256>>>(x, bw1, sw1, sc1, H);
    }
    // -------- Layer 2 (split-K = 2) --------
    {
        int cpr = (IN2 + 31) / 32;                        // 65
        int nw = MROWS * cpr;
        expA<<<(nw + 7) / 8, 256>>>(H, NPAD1, IN2, KP2, cpr, A2, APS2, ACH, nw);
        int nww = OUT2 * cpr;
        expW<<<(nww + 7) / 8, 256>>>(bw2, sw2, sc2, OUT2, IN2, KP2, cpr, B2, BPS2, BCH2, nww);
        int ksplit = (NCH2 + 1) / 2;                      // 145
        gemm_mma<<<dim3(OUT2 / 256, MROWS / 128, 2), 256, SMEM>>>(
            A2, APS2, ACH, B2, BPS2, BCH2, P, OUT2, NCH2, ksplit, ZPL);
        int n4 = (MROWS * OUT2) / 4;
        addP<<<(n4 + 255) / 256, 256>>>(P, ZPL, out, n4);
    }
}

// round 12
// speedup vs baseline: 3.4395x; 1.0061x over previous
#include <cuda_runtime.h>
#include <cuda_bf16.h>
#include <cstdint>

#define MROWS 4096
#define IN1   512
#define OUT1  2049
#define NGEMM1 2048         // GEMM cols 0..2047; col 2048 via fp32 GEMV
#define NPAD1 2304          // H row stride
#define KP1   4608          // IN1*9 = 72 chunks of 64
#define NCH1  72
#define IN2   2049
#define OUT2  512
#define KR2   18441
#define KP2   18496         // 289 chunks of 64
#define NCH2  289
#define RW    72            // bf16 per row per chunk (64 real + 8 pad)

// chunk-major staging: [plane][kchunk][row][RW]
#define ACH   ((size_t)MROWS * RW)              // chunk stride (elements)
#define BCH1  ((size_t)NGEMM1 * RW)
#define BCH2  ((size_t)OUT2 * RW)
#define APS1  ((size_t)NCH1 * ACH)
#define BPS1  ((size_t)NCH1 * BCH1)
#define APS2  ((size_t)NCH2 * ACH)
#define BPS2  ((size_t)NCH2 * BCH2)

__device__ __align__(128) __nv_bfloat16 g_A1[2 * APS1];
__device__ __align__(128) __nv_bfloat16 g_B1[2 * BPS1];
__device__ __align__(128) float         g_H [(size_t)MROWS * NPAD1];
__device__ __align__(128) __nv_bfloat16 g_A2[2 * APS2];
__device__ __align__(128) __nv_bfloat16 g_B2[2 * BPS2];
__device__ __align__(128) float         g_P [2ull * MROWS * OUT2];

// ------------------------------------------------------------- helpers
__device__ __forceinline__ uint32_t smem_u32(const void* p) {
    uint32_t a;
    asm("{ .reg .u64 t; cvta.to.shared.u64 t, %1; cvt.u32.u64 %0, t; }" : "=r"(a) : "l"(p));
    return a;
}
__device__ __forceinline__ void mbar_init(uint32_t a, uint32_t c) {
    asm volatile("mbarrier.init.shared.b64 [%0], %1;" :: "r"(a), "r"(c) : "memory");
}
__device__ __forceinline__ void mbar_wait(uint32_t a, uint32_t par) {
    uint32_t done = 0;
    while (!done)
        asm volatile("{\n\t.reg .pred P;\n\t"
            "mbarrier.try_wait.parity.acquire.cta.shared::cta.b64 P, [%1], %2, 0x989680;\n\t"
            "selp.b32 %0, 1, 0, P;\n\t}" : "=r"(done) : "r"(a), "r"(par) : "memory");
}
__device__ __forceinline__ void bulk_g2s(uint32_t dst, const void* src, uint32_t bytes, uint32_t mb) {
    asm volatile("cp.async.bulk.shared::cluster.global.mbarrier::complete_tx::bytes "
                 "[%0], [%1], %2, [%3];"
                 :: "r"(dst), "l"(src), "r"(bytes), "r"(mb) : "memory");
}
__device__ __forceinline__ void ldm_x4(uint32_t a, uint32_t& r0, uint32_t& r1,
                                       uint32_t& r2, uint32_t& r3) {
    asm volatile("ldmatrix.sync.aligned.m8n8.x4.shared.b16 {%0,%1,%2,%3}, [%4];"
                 : "=r"(r0), "=r"(r1), "=r"(r2), "=r"(r3) : "r"(a));
}
__device__ __forceinline__ void mma16816(float* d, const uint32_t* a, const uint32_t* b) {
    asm volatile(
        "mma.sync.aligned.m16n8k16.row.col.f32.bf16.bf16.f32 "
        "{%0,%1,%2,%3}, {%4,%5,%6,%7}, {%8,%9}, {%0,%1,%2,%3};"
        : "+f"(d[0]), "+f"(d[1]), "+f"(d[2]), "+f"(d[3])
        : "r"(a[0]), "r"(a[1]), "r"(a[2]), "r"(a[3]), "r"(b[0]), "r"(b[1]));
}

// ------------------------------------------------------------- expansion math
__device__ __forceinline__ void expand9(float x, float v[9]) {
#pragma unroll
    for (int j = 0; j < 9; j++) v[j] = 0.0f;
    v[0] = x / (1.0f + __expf(-x));                       // SiLU
    if (x >= -2.2f && x < 2.2f) {                         // uniform cubic B-spline
        float xm = (x + 2.2f) * 2.5f;
        float fm = floorf(xm);
        int s = (int)fm;
        float u = xm - fm, u2 = u * u, u3 = u2 * u, w = 1.0f - u;
        float nn[4];
        nn[0] = w * w * w * (1.0f / 6.0f);
        nn[1] = fmaf(u3, 0.5f, fmaf(u2, -1.0f, 2.0f / 3.0f));
        nn[2] = fmaf(u3, -0.5f, fmaf(u2, 0.5f, fmaf(u, 0.5f, 1.0f / 6.0f)));
        nn[3] = u3 * (1.0f / 6.0f);
#pragma unroll
        for (int d = 0; d < 4; d++) {
            int t = s - 3 + d;
            if ((unsigned)t < 8u) v[1 + t] = nn[d];
        }
    }
}
__device__ __forceinline__ void wsplit(float f, __nv_bfloat16& h, __nv_bfloat16& l) {
    h = __float2bfloat16(f);
    l = __float2bfloat16(f - __bfloat162float(h));
}

// write one warp's 288-k span from smem staging into chunk-major layout
__device__ __forceinline__ void store_span(const __nv_bfloat16* sh, const __nv_bfloat16* sl,
                                           __nv_bfloat16* D, size_t PS, size_t CHS,
                                           int row, int k0, int KP, int lane) {
    int span = KP - k0; if (span > 288) span = 288;
    int off = 0;
    while (off < span) {
        int k = k0 + off;
        int ki = k >> 6, kin = k & 63;
        int len = 64 - kin; if (len > span - off) len = span - off;
        __nv_bfloat16* dh = D + (size_t)ki * CHS + (size_t)row * RW + kin;
        const uint4* s0 = (const uint4*)(sh + off);
        const uint4* s1 = (const uint4*)(sl + off);
        int n4 = len >> 3;
        for (int idx = lane; idx < n4; idx += 32) {
            ((uint4*)dh)[idx] = s0[idx];
            ((uint4*)(dh + PS))[idx] = s1[idx];
        }
        off += len;
    }
}

// ------------------------------------------------------------- expansion kernels
__global__ void __launch_bounds__(256)
expA(const float* __restrict__ X, int ldx, int IN, int KP, int CPR,
     __nv_bfloat16* __restrict__ A, size_t PS, size_t CHS, int nwarps) {
    __shared__ __align__(16) __nv_bfloat16 sh[8][288];
    __shared__ __align__(16) __nv_bfloat16 sl[8][288];
    int wl = threadIdx.x >> 5, lane = threadIdx.x & 31;
    int w = blockIdx.x * 8 + wl;
    if (w >= nwarps) return;
    int row = w / CPR, ic = w - row * CPR;
    int i0 = ic * 32, i = i0 + lane;
    float v[9];
    if (i < IN) expand9(X[(size_t)row * ldx + i], v);
    else {
#pragma unroll
        for (int j = 0; j < 9; j++) v[j] = 0.0f;
    }
#pragma unroll
    for (int j = 0; j < 9; j++) {
        __nv_bfloat16 h, l; wsplit(v[j], h, l);
        sh[wl][lane * 9 + j] = h; sl[wl][lane * 9 + j] = l;
    }
    __syncwarp();
    store_span(sh[wl], sl[wl], A, PS, CHS, row, i0 * 9, KP, lane);
}

__global__ void __launch_bounds__(256)
expW(const float* __restrict__ BW, const float* __restrict__ SW,
     const float* __restrict__ SC, int OUT, int IN, int KP, int CPR,
     __nv_bfloat16* __restrict__ B, size_t PS, size_t CHS, int nwarps) {
    __shared__ __align__(16) __nv_bfloat16 sh[8][288];
    __shared__ __align__(16) __nv_bfloat16 sl[8][288];
    int wl = threadIdx.x >> 5, lane = threadIdx.x & 31;
    int w = blockIdx.x * 8 + wl;
    if (w >= nwarps) return;
    int o = w / CPR, ic = w - o * CPR;
    int i0 = ic * 32, i = i0 + lane;
    float v[9];
    if (i < IN && o < OUT) {
        size_t oi = (size_t)o * IN + i;
        float s = SC[oi];
        v[0] = BW[oi];
        const float* sw = SW + oi * 8;
#pragma unroll
        for (int j = 0; j < 8; j++) v[1 + j] = sw[j] * s;
    } else {
#pragma unroll
        for (int j = 0; j < 9; j++) v[j] = 0.0f;
    }
#pragma unroll
    for (int j = 0; j < 9; j++) {
        __nv_bfloat16 h, l; wsplit(v[j], h, l);
        sh[wl][lane * 9 + j] = h; sl[wl][lane * 9 + j] = l;
    }
    __syncwarp();
    store_span(sh[wl], sl[wl], B, PS, CHS, o, i0 * 9, KP, lane);
}

// fp32 GEMV for layer-1 output column 2048 (exact, one warp per row)
__global__ void __launch_bounds__(256)
gemv_col(const float* __restrict__ X, const float* __restrict__ BW,
         const float* __restrict__ SW, const float* __restrict__ SC,
         float* __restrict__ H) {
    const int col = NGEMM1;
    int w = blockIdx.x * 8 + (threadIdx.x >> 5);
    int lane = threadIdx.x & 31;
    if (w >= MROWS) return;
    const float* xr = X + (size_t)w * IN1;
    float acc = 0.0f;
    for (int i = lane; i < IN1; i += 32) {
        float v[9];
        expand9(xr[i], v);
        size_t oi = (size_t)col * IN1 + i;
        acc = fmaf(v[0], BW[oi], acc);
        float s = SC[oi];
        const float* swp = SW + oi * 8;
#pragma unroll
        for (int j = 0; j < 8; j++) acc = fmaf(v[1 + j] * s, swp[j], acc);
    }
#pragma unroll
    for (int o = 16; o; o >>= 1) acc += __shfl_xor_sync(0xFFFFFFFFu, acc, o);
    if (lane == 0) H[(size_t)w * NPAD1 + col] = acc;
}

// split-K reduce
__global__ void __launch_bounds__(256)
addP(const float* __restrict__ P, size_t plane, float* __restrict__ out, int n4) {
    int t = blockIdx.x * blockDim.x + threadIdx.x;
    if (t >= n4) return;
    float4 a = ((const float4*)P)[t];
    float4 b = ((const float4*)(P + plane))[t];
    ((float4*)out)[t] = make_float4(a.x + b.x, a.y + b.y, a.z + b.z, a.w + b.w);
}

// ------------------------------------------------------------- MMA GEMM
// D = A @ B^T, chunk-major inputs: A[ki][m][RW] (hi plane, lo at +APS), B likewise.
// 4 cp.async.bulk per chunk + mbarrier. 3-pass bf16 hi/lo split, fp32 accum.
// CTA 128x256, 8 warps (2m x 4n), 2-stage. MMA issue is pass-major so
// dependent HMMAs on the same accumulator are 8 independent issues apart.
__global__ void __launch_bounds__(256, 1)
gemm_mma(const __nv_bfloat16* __restrict__ A, size_t APS, size_t ACHs,
         const __nv_bfloat16* __restrict__ B, size_t BPS, size_t BCHs,
         float* __restrict__ C, int Nld, int KTOT, int KSPLIT, size_t zplane) {
    constexpr int BM = 128, BN = 256;
    constexpr int WM = 64, WN = 64, MT = 4, NT = 8;
    constexpr int LDS = 144;
    constexpr int SA = BM * LDS;            // 18432
    constexpr int SB = BN * LDS;            // 36864
    constexpr int STAGE = 2 * SA + 2 * SB;  // 110592

    extern __shared__ __align__(128) char smc[];
    __shared__ __align__(8) uint64_t mbar_s[2];
    const uint32_t sbase = smem_u32(smc);
    const uint32_t mb0 = smem_u32(&mbar_s[0]);
    const int tid = threadIdx.x;
    const int lane = tid & 31, wid = tid >> 5;
    const int wm = wid >> 2, wn = wid & 3;
    const int row0 = blockIdx.y * BM, col0 = blockIdx.x * BN;

    const int kstart = blockIdx.z * KSPLIT;
    int kit = KTOT - kstart; if (kit > KSPLIT) kit = KSPLIT;
    float* Cz = C + blockIdx.z * zplane;

    if (tid == 0) { mbar_init(mb0, 1); mbar_init(mb0 + 8, 1); }
    __syncthreads();

    auto issue = [&](int stg, int it) {
        uint32_t mb = mb0 + stg * 8;
        asm volatile("mbarrier.arrive.expect_tx.shared.b64 _, [%0], %1;"
                     :: "r"(mb), "r"((uint32_t)STAGE) : "memory");
        size_t ki = (size_t)(kstart + it);
        uint32_t sb = sbase + stg * STAGE;
        const __nv_bfloat16* ah = A + ki * ACHs + (size_t)row0 * RW;
        const __nv_bfloat16* bh = B + ki * BCHs + (size_t)col0 * RW;
        bulk_g2s(sb,               ah,        SA, mb);
        bulk_g2s(sb + SA,          ah + APS,  SA, mb);
        bulk_g2s(sb + 2 * SA,      bh,        SB, mb);
        bulk_g2s(sb + 2 * SA + SB, bh + BPS,  SB, mb);
    };

    // ldmatrix lane offsets within a stage
    uint32_t offA[MT], offB[NT / 2];
#pragma unroll
    for (int mt = 0; mt < MT; mt++)
        offA[mt] = (uint32_t)((wm * WM + mt * 16 + (lane & 15)) * LDS + ((lane >> 4) * 16));
#pragma unroll
    for (int np = 0; np < NT / 2; np++)
        offB[np] = (uint32_t)(2 * SA +
                   (wn * WN + np * 16 + ((lane >> 4) * 8) + (lane & 7)) * LDS +
                   (((lane >> 3) & 1) * 16));

    float acc[MT][NT][4];
#pragma unroll
    for (int i = 0; i < MT; i++)
#pragma unroll
        for (int j = 0; j < NT; j++)
#pragma unroll
            for (int k = 0; k < 4; k++) acc[i][j][k] = 0.0f;

    if (tid == 0) issue(0, 0);

    for (int it = 0; it < kit; it++) {
        const int stg = it & 1;
        if (it + 1 < kit) {
            __syncthreads();                       // all warps done with buffer stg^1
            if (tid == 0) issue(stg ^ 1, it + 1);
        }
        mbar_wait(mb0 + stg * 8, (it >> 1) & 1);

        const uint32_t sb = sbase + stg * STAGE;
#pragma unroll
        for (int s = 0; s < 4; s++) {              // 4 k-steps of 16
            uint32_t ah[MT][4], al[MT][4];
#pragma unroll
            for (int mt = 0; mt < MT; mt++) {
                uint32_t a0 = sb + offA[mt] + s * 32;
                ldm_x4(a0, ah[mt][0], ah[mt][1], ah[mt][2], ah[mt][3]);
                ldm_x4(a0 + SA, al[mt][0], al[mt][1], al[mt][2], al[mt][3]);
            }
#pragma unroll
            for (int np = 0; np < NT / 2; np++) {
                uint32_t bh[2][2], bl[2][2];
                uint32_t b0 = sb + offB[np] + s * 32;
                ldm_x4(b0, bh[0][0], bh[0][1], bh[1][0], bh[1][1]);
                ldm_x4(b0 + SB, bl[0][0], bl[0][1], bl[1][0], bl[1][1]);
                // pass-major: dependent MMAs on the same acc are 8 issues apart
#pragma unroll
                for (int pass = 0; pass < 3; pass++)
#pragma unroll
                    for (int q = 0; q < 2; q++)
#pragma unroll
                        for (int mt = 0; mt < MT; mt++) {
                            const uint32_t* aa = (pass == 2) ? al[mt] : ah[mt];
                            const uint32_t* bb = (pass == 1) ? bl[q] : bh[q];
                            mma16816(acc[mt][2 * np + q], aa, bb);
                        }
            }
        }
    }

    // epilogue
#pragma unroll
    for (int mt = 0; mt < MT; mt++)
#pragma unroll
        for (int nt = 0; nt < NT; nt++) {
            int r = row0 + wm * WM + mt * 16 + (lane >> 2);
            int c = col0 + wn * WN + nt * 8 + ((lane & 3) << 1);
            *(float2*)&Cz[(size_t)r * Nld + c] = make_float2(acc[mt][nt][0], acc[mt][nt][1]);
            *(float2*)&Cz[(size_t)(r + 8) * Nld + c] = make_float2(acc[mt][nt][2], acc[mt][nt][3]);
        }
}

// ---------------------------------------------------------------------------
extern "C" void kernel_launch(void* const* d_in, const int* in_sizes, int n_in,
                              void* d_out, int out_size) {
    const float* x   = (const float*)d_in[0];
    const float* bw1 = (const float*)d_in[1];
    const float* sw1 = (const float*)d_in[2];
    const float* sc1 = (const float*)d_in[3];
    const float* bw2 = (const float*)d_in[4];
    const float* sw2 = (const float*)d_in[5];
    const float* sc2 = (const float*)d_in[6];
    float* out = (float*)d_out;

    __nv_bfloat16 *A1, *B1, *A2, *B2;
    float *H, *P;
    cudaGetSymbolAddress((void**)&A1, g_A1);
    cudaGetSymbolAddress((void**)&B1, g_B1);
    cudaGetSymbolAddress((void**)&H,  g_H);
    cudaGetSymbolAddress((void**)&A2, g_A2);
    cudaGetSymbolAddress((void**)&B2, g_B2);
    cudaGetSymbolAddress((void**)&P,  g_P);

    const size_t ZPL = (size_t)MROWS * OUT2;
    const int SMEM = 2 * (2 * 128 * 144 + 2 * 256 * 144);   // 221184
    cudaFuncSetAttribute((const void*)gemm_mma,
                         cudaFuncAttributeMaxDynamicSharedMemorySize, SMEM);

    // -------- Layer 1 --------
    {
        int cpr = (IN1 + 31) / 32;                        // 16
        int nw = MROWS * cpr;
        expA<<<(nw + 7) / 8, 256>>>(x, IN1, IN1, KP1, cpr, A1, APS1, ACH, nw);
        int nww = NGEMM1 * cpr;
        expW<<<(nww + 7) / 8, 256>>>(bw1, sw1, sc1, NGEMM1, IN1, KP1, cpr, B1, BPS1, BCH1, nww);
        gemm_mma<<<dim3(NGEMM1 / 256, MROWS / 128, 1), 256, SMEM>>>(
            A1, APS1, ACH, B1, BPS1, BCH1, H, NPAD1, NCH1, NCH1, 0);
        gemv_col<<<MROWS / 8, 256>>>(x, bw1, sw1, sc1, H);
    }
    // -------- Layer 2 (split-K = 2) --------
    {
        int cpr = (IN2 + 31) / 32;                        // 65
        int nw = MROWS * cpr;
        expA<<<(nw + 7) / 8, 256>>>(H, NPAD1, IN2, KP2, cpr, A2, APS2, ACH, nw);
        int nww = OUT2 * cpr;
        expW<<<(nww + 7) / 8, 256>>>(bw2, sw2, sc2, OUT2, IN2, KP2, cpr, B2, BPS2, BCH2, nww);
        int ksplit = (NCH2 + 1) / 2;                      // 145
        gemm_mma<<<dim3(OUT2 / 256, MROWS / 128, 2), 256, SMEM>>>(
            A2, APS2, ACH, B2, BPS2, BCH2, P, OUT2, NCH2, ksplit, ZPL);
        int n4 = (MROWS * OUT2) / 4;
        addP<<<(n4 + 255) / 256, 256>>>(P, ZPL, out, n4);
    }
}